// round 10
// baseline (speedup 1.0000x reference)
#include <cuda_runtime.h>
#include <cuda_fp16.h>
#include <math.h>
#include <stdint.h>

#define BB   128
#define TT   200
#define VV   50257
#define VVP  50264          // half row stride, 16B-aligned rows
#define HH   256
#define EE   128
#define NOOV 50
#define G3   768
#define VO   (VV + NOOV)
#define BT   (BB * TT)
#define SPAD 36             // tf32 gates kernel smem stride (words)

#define NBG  393            // score_g tiles 128x128 (first)
#define NBE  400            // enc tiles 64x256

#define STG_G ((128 + 128) * SPAD)   // gates stage words
#define DYN_GATES (2 * STG_G * 4)

// fp16 k_big smem: row stride 40 halfs (80B) -> conflict-free LDSM
#define KS2      40
#define STGB_G   (256 * KS2 * 2)     // 20480 B (128 A + 128 W rows)
#define STGB_E   (320 * KS2 * 2)     // 25600 B (64 A + 256 W rows)
#define DYN_BIG  (2 * STGB_E)        // 51200 B

// ---------------- scratch ----------------------------------------------
__device__ float  g_gi[BB * G3];
__device__ float  g_gh[BB * G3];
__device__ float  g_dh[BB * HH];
__device__ __half g_dhh[BB * HH];
__device__ __half g_wgh[(size_t)VV * HH];     // fp16 Wg
__device__ __half g_wch[256 * 512];            // fp16 Wc
__device__ __half g_eoh[(size_t)BT * 512];     // fp16 encoder_outputs
__device__ __half g_scoreh[BB * VVP];
__device__ float  g_scraw[BT];
__device__ float  g_pmax[BB * NBG];
__device__ float  g_psum[BB * NBG];
__device__ float  g_M[BB];
__device__ float  g_invS[BB];

// ---------------- helpers ------------------------------------------------
__device__ __forceinline__ void mma8(float* c, const uint32_t* a, const uint32_t* b) {
    asm volatile(
        "mma.sync.aligned.m16n8k8.row.col.f32.tf32.tf32.f32 "
        "{%0,%1,%2,%3}, {%4,%5,%6,%7}, {%8,%9}, {%0,%1,%2,%3};\n"
        : "+f"(c[0]), "+f"(c[1]), "+f"(c[2]), "+f"(c[3])
        : "r"(a[0]), "r"(a[1]), "r"(a[2]), "r"(a[3]), "r"(b[0]), "r"(b[1]));
}
__device__ __forceinline__ void mma16(float* c, const uint32_t* a, const uint32_t* b) {
    asm volatile(
        "mma.sync.aligned.m16n8k16.row.col.f32.f16.f16.f32 "
        "{%0,%1,%2,%3}, {%4,%5,%6,%7}, {%8,%9}, {%0,%1,%2,%3};\n"
        : "+f"(c[0]), "+f"(c[1]), "+f"(c[2]), "+f"(c[3])
        : "r"(a[0]), "r"(a[1]), "r"(a[2]), "r"(a[3]), "r"(b[0]), "r"(b[1]));
}
__device__ __forceinline__ void ldsm4(uint32_t& r0, uint32_t& r1, uint32_t& r2,
                                      uint32_t& r3, uint32_t addr) {
    asm volatile("ldmatrix.sync.aligned.m8n8.x4.shared.b16 {%0,%1,%2,%3}, [%4];\n"
                 : "=r"(r0), "=r"(r1), "=r"(r2), "=r"(r3) : "r"(addr));
}
__device__ __forceinline__ void cpa16(uint32_t saddr, const void* g, int srcsz) {
    asm volatile("cp.async.ca.shared.global [%0], [%1], 16, %2;\n"
                 :: "r"(saddr), "l"(g), "r"(srcsz));
}
__device__ __forceinline__ void cp_commit() { asm volatile("cp.async.commit_group;\n"); }
__device__ __forceinline__ void cp_wait1()  { asm volatile("cp.async.wait_group 1;\n"); }
__device__ __forceinline__ void osm(float& m, float& s, float om, float os) {
    float M = fmaxf(m, om);
    s = s * __expf(m - M) + os * __expf(om - M);
    m = M;
}

// ---------------- fp16 k_big: cp.async stage loader -------------------------
// rows: nA A-rows then nW W-rows, 32 halfs (64B) per row = 4 x 16B chunks
__device__ __forceinline__ void load_stage_h(uint32_t s0,
        int nA, const __half* __restrict__ A, int lda,
        const __half* __restrict__ W, int ldw, int wvalid, int nW,
        int k0, int tid) {
    int total = (nA + nW) * 4;
    for (int idx = tid; idx < total; idx += 256) {
        int row = idx >> 2, kp = (idx & 3) * 8;
        uint32_t dst = s0 + (uint32_t)(row * KS2 + kp) * 2;
        if (row < nA) {
            cpa16(dst, A + (size_t)row * lda + k0 + kp, 16);
        } else {
            int wr = row - nA;
            int ok = wr < wvalid;
            const __half* src = W + (size_t)(ok ? wr : 0) * ldw + k0 + kp;
            cpa16(dst, src, ok ? 16 : 0);
        }
    }
}
// ldmatrix x4: rows rowbase..+15, k-halfs kk*16..+15 (matches mma16 frag order)
__device__ __forceinline__ void frag_ldsm(uint32_t* r, uint32_t s0, int rowbase,
                                          int kk, int lane) {
    int lr  = lane & 7;
    int row = rowbase + ((lane >> 3) & 1) * 8 + lr;
    uint32_t addr = s0 + (uint32_t)(row * KS2 + kk * 16 + (lane >> 4) * 8) * 2;
    ldsm4(r[0], r[1], r[2], r[3], addr);
}
// one k16 step of the 32x64 warp tile
__device__ __forceinline__ void compute_k16(uint32_t s0, int nA, int wm, int wn,
                                            int kk, int lane, float c[2][8][4]) {
    uint32_t a[2][4];
    frag_ldsm(a[0], s0, wm,      kk, lane);
    frag_ldsm(a[1], s0, wm + 16, kk, lane);
#pragma unroll
    for (int jj = 0; jj < 4; jj++) {
        uint32_t r[4];
        frag_ldsm(r, s0, nA + wn + jj * 16, kk, lane);
        uint32_t b0[2] = {r[0], r[2]}, b1[2] = {r[1], r[3]};
#pragma unroll
        for (int i = 0; i < 2; i++) {
            mma16(c[i][jj * 2],     a[i], b0);
            mma16(c[i][jj * 2 + 1], a[i], b1);
        }
    }
}

// ---------------- converter: fp32 -> fp16 for Wg, Wc, EO --------------------
__global__ void __launch_bounds__(256) k_conv(
        const float* __restrict__ Wg, const float* __restrict__ Wc,
        const float* __restrict__ EO) {
    const size_t n1 = (size_t)VV * HH / 4;
    const size_t n2 = n1 + (256 * 512) / 4;
    const size_t n3 = n2 + (size_t)BT * 512 / 4;
    size_t stride = (size_t)gridDim.x * blockDim.x;
    for (size_t k = (size_t)blockIdx.x * blockDim.x + threadIdx.x; k < n3; k += stride) {
        const float4* src; __half2* dst; size_t off;
        if (k < n1)      { src = (const float4*)Wg; dst = (__half2*)g_wgh; off = k; }
        else if (k < n2) { src = (const float4*)Wc; dst = (__half2*)g_wch; off = k - n1; }
        else             { src = (const float4*)EO; dst = (__half2*)g_eoh; off = k - n2; }
        float4 v = src[off];
        dst[off * 2]     = __floats2half2_rn(v.x, v.y);
        dst[off * 2 + 1] = __floats2half2_rn(v.z, v.w);
    }
}

// ---------------- tf32 warp mma (gates kernel only) -------------------------
__device__ __forceinline__ void warp_mma(const uint32_t* __restrict__ sA,
                                         const uint32_t* __restrict__ sW,
                                         int wm, int wn, int g, int t,
                                         float c[2][8][4]) {
#pragma unroll
    for (int kk = 0; kk < 4; kk++) {
        int kb = kk * 8;
        uint32_t a[2][4];
#pragma unroll
        for (int i = 0; i < 2; i++) {
            int r = wm + i * 16 + g;
            a[i][0] = sA[r * SPAD + kb + t];     a[i][1] = sA[(r + 8) * SPAD + kb + t];
            a[i][2] = sA[r * SPAD + kb + t + 4]; a[i][3] = sA[(r + 8) * SPAD + kb + t + 4];
        }
        uint32_t bf[8][2];
#pragma unroll
        for (int j = 0; j < 8; j++) {
            int n = wn + j * 8 + g;
            bf[j][0] = sW[n * SPAD + kb + t]; bf[j][1] = sW[n * SPAD + kb + t + 4];
        }
#pragma unroll
        for (int i = 0; i < 2; i++)
#pragma unroll
            for (int j = 0; j < 8; j++) mma8(c[i][j], a[i], bf[j]);
    }
}

// ---------------- gates: gi = [sr|emb] @ W_ih^T + b ; gh = prev @ W_hh^T + b
__global__ void __launch_bounds__(256, 2) k_gates(
        const int* __restrict__ dec, const float* __restrict__ sr,
        const float* __restrict__ emb, const float* __restrict__ prev,
        const float* __restrict__ W_ih, const float* __restrict__ b_ih,
        const float* __restrict__ W_hh, const float* __restrict__ b_hh) {
    extern __shared__ uint32_t dyn[];
    uint32_t sbase = (uint32_t)__cvta_generic_to_shared(dyn);
    int tid = threadIdx.x, wid = tid >> 5, lane = tid & 31;
    int g = lane >> 2, t = lane & 3;
    int wm = (wid & 3) * 32, wn = (wid >> 2) * 64;
    int bx = blockIdx.x;
    bool isGi = bx < 6;
    int n0 = (isGi ? bx : bx - 6) * 128;
    int K  = isGi ? 640 : HH;
    int NIT = K / 32;
    const float* W = (isGi ? W_ih : W_hh) + (size_t)n0 * K;
    const float* bias = isGi ? b_ih : b_hh;
    float* C = isGi ? g_gi : g_gh;

    float c[2][8][4];
#pragma unroll
    for (int i = 0; i < 2; i++)
#pragma unroll
        for (int j = 0; j < 8; j++)
#pragma unroll
            for (int q = 0; q < 4; q++) c[i][j][q] = 0.f;

    auto loadA = [&](int stage, int k0) {
        uint32_t s0 = sbase + (uint32_t)stage * (STG_G * 4);
        if (isGi) {
            for (int idx = tid; idx < 1024; idx += 256) {
                int row = idx >> 3, kp = (idx & 7) * 4;
                const float* src;
                if (k0 < 512) src = sr + (size_t)row * 512 + k0 + kp;
                else          src = emb + (size_t)dec[row] * EE + (k0 - 512) + kp;
                cpa16(s0 + (row * SPAD + kp) * 4, src, 16);
            }
        } else {
            for (int idx = tid; idx < 1024; idx += 256) {
                int row = idx >> 3, kp = (idx & 7) * 4;
                cpa16(s0 + (row * SPAD + kp) * 4, prev + (size_t)row * HH + k0 + kp, 16);
            }
        }
        for (int idx = tid; idx < 1024; idx += 256) {
            int row = idx >> 3, kp = (idx & 7) * 4;
            cpa16(s0 + ((128 + row) * SPAD + kp) * 4, W + (size_t)row * K + k0 + kp, 16);
        }
    };

    loadA(0, 0);  cp_commit();
    loadA(1, 32); cp_commit();
    for (int it = 0; it < NIT; it++) {
        cp_wait1();
        __syncthreads();
        const uint32_t* s = dyn + (it & 1) * STG_G;
        warp_mma(s, s + 128 * SPAD, wm, wn, g, t, c);
        __syncthreads();
        if (it + 2 < NIT) loadA(it & 1, (it + 2) * 32);
        cp_commit();
    }
#pragma unroll
    for (int i = 0; i < 2; i++) {
        int r = wm + i * 16 + g;
#pragma unroll
        for (int j = 0; j < 8; j++) {
            int col = n0 + wn + j * 8 + 2 * t;
            float b0 = bias[col], b1 = bias[col + 1];
            C[(size_t)r * G3 + col]           = c[i][j][0] + b0;
            C[(size_t)r * G3 + col + 1]       = c[i][j][1] + b1;
            C[(size_t)(r + 8) * G3 + col]     = c[i][j][2] + b0;
            C[(size_t)(r + 8) * G3 + col + 1] = c[i][j][3] + b1;
        }
    }
}

// ---------------- GRU gate fusion (also emits fp16 dh) ----------------------
__global__ void k_gru(const float* __restrict__ hprev, float* __restrict__ out_dh) {
    int b = blockIdx.x, j = threadIdx.x;
    const float* gi = g_gi + b * G3;
    const float* gh = g_gh + b * G3;
    float r  = 1.f / (1.f + expf(-(gi[j] + gh[j])));
    float z  = 1.f / (1.f + expf(-(gi[HH+j] + gh[HH+j])));
    float n  = tanhf(gi[2*HH+j] + r * gh[2*HH+j]);
    float h  = hprev[b * HH + j];
    float dh = (1.f - z) * n + z * h;
    g_dh[b*HH+j]   = dh;
    g_dhh[b*HH+j]  = __float2half_rn(dh);
    out_dh[b*HH+j] = dh;
}

// ---------------- big fused fp16 tensor-core kernel (cp.async fill) ---------
// bx < NBG : score_g tile 128x128, K=256 ; else : enc tile 64x256, K=512
__global__ void __launch_bounds__(256, 2) k_big(
        const float* __restrict__ gbias, const float* __restrict__ cbias,
        const int* __restrict__ idxs) {
    extern __shared__ uint32_t dyn[];
    uint32_t sbase = (uint32_t)__cvta_generic_to_shared(dyn);
    int tid = threadIdx.x, wid = tid >> 5, lane = tid & 31;
    int g = lane >> 2, t = lane & 3;
    int bx = blockIdx.x;
    bool isg = bx < NBG;

    int wm, wn, nA, NIT, wvalid, nW, lda, stgB;
    const __half* A; const __half* W; int ldw;
    if (isg) {
        wm = (wid & 3) * 32; wn = (wid >> 2) * 64;
        A = g_dhh; lda = HH; nA = 128;
        W = g_wgh + (size_t)bx * 128 * HH; ldw = HH; nW = 128;
        wvalid = VV - bx * 128; if (wvalid > 128) wvalid = 128;
        NIT = HH / 32; stgB = STGB_G;
    } else {
        wm = (wid & 1) * 32; wn = (wid >> 1) * 64;
        int r0 = (bx - NBG) * 64;
        A = g_eoh + (size_t)r0 * (2 * HH); lda = 2 * HH; nA = 64;
        W = g_wch; ldw = 2 * HH; nW = 256; wvalid = 256;
        NIT = (2 * HH) / 32; stgB = STGB_E;
    }

    float c[2][8][4];
#pragma unroll
    for (int i = 0; i < 2; i++)
#pragma unroll
        for (int j = 0; j < 8; j++)
#pragma unroll
            for (int q = 0; q < 4; q++) c[i][j][q] = 0.f;

    load_stage_h(sbase,                  nA, A, lda, W, ldw, wvalid, nW, 0,  tid); cp_commit();
    load_stage_h(sbase + (uint32_t)stgB, nA, A, lda, W, ldw, wvalid, nW, 32, tid); cp_commit();

    for (int it = 0; it < NIT; it++) {
        cp_wait1();
        __syncthreads();
        uint32_t scur = sbase + (uint32_t)(it & 1) * stgB;
        compute_k16(scur, nA, wm, wn, 0, lane, c);
        compute_k16(scur, nA, wm, wn, 1, lane, c);
        __syncthreads();
        if (it + 2 < NIT)
            load_stage_h(sbase + (uint32_t)(it & 1) * stgB,
                         nA, A, lda, W, ldw, wvalid, nW, (it + 2) * 32, tid);
        cp_commit();
    }

    if (isg) {
        // ---- epilogue: half store (+bias) and per-tile online (max, sumexp) --
        int n0 = bx * 128;
        float lm[2][2], ls[2][2];
#pragma unroll
        for (int i = 0; i < 2; i++)
#pragma unroll
            for (int h = 0; h < 2; h++) { lm[i][h] = -1e30f; ls[i][h] = 0.f; }
#pragma unroll
        for (int i = 0; i < 2; i++) {
            int r = wm + i * 16 + g;
#pragma unroll
            for (int j = 0; j < 8; j++) {
                int col = n0 + wn + j * 8 + 2 * t;
                if (col < VV) {
                    bool p1 = (col + 1 < VV);
                    float b0 = gbias[col];
                    float b1 = p1 ? gbias[col + 1] : 0.f;
                    __half2 h02 = __floats2half2_rn(c[i][j][0] + b0, c[i][j][1] + b1);
                    __half2 h23 = __floats2half2_rn(c[i][j][2] + b0, c[i][j][3] + b1);
                    *(__half2*)(g_scoreh + (size_t)r * VVP + col)       = h02;
                    *(__half2*)(g_scoreh + (size_t)(r + 8) * VVP + col) = h23;
                    float w0 = __half2float(__low2half(h02));
                    float w1 = __half2float(__high2half(h02));
                    float w2 = __half2float(__low2half(h23));
                    float w3 = __half2float(__high2half(h23));
                    lm[i][0] = fmaxf(lm[i][0], w0);
                    lm[i][1] = fmaxf(lm[i][1], w2);
                    if (p1) { lm[i][0] = fmaxf(lm[i][0], w1); lm[i][1] = fmaxf(lm[i][1], w3); }
                }
            }
        }
#pragma unroll
        for (int i = 0; i < 2; i++)
#pragma unroll
            for (int j = 0; j < 8; j++) {
                int col = n0 + wn + j * 8 + 2 * t;
                if (col < VV) {
                    bool p1 = (col + 1 < VV);
                    float b0 = gbias[col];
                    float b1 = p1 ? gbias[col + 1] : 0.f;
                    float w0 = __half2float(__float2half_rn(c[i][j][0] + b0));
                    float w2 = __half2float(__float2half_rn(c[i][j][2] + b0));
                    ls[i][0] += __expf(w0 - lm[i][0]);
                    ls[i][1] += __expf(w2 - lm[i][1]);
                    if (p1) {
                        float w1 = __half2float(__float2half_rn(c[i][j][1] + b1));
                        float w3 = __half2float(__float2half_rn(c[i][j][3] + b1));
                        ls[i][0] += __expf(w1 - lm[i][0]);
                        ls[i][1] += __expf(w3 - lm[i][1]);
                    }
                }
            }
        __syncthreads();
        float* redm = (float*)dyn;           // [128][2]
        float* reds = redm + 256;
#pragma unroll
        for (int i = 0; i < 2; i++)
#pragma unroll
            for (int h = 0; h < 2; h++) {
                float m = lm[i][h], s = ls[i][h];
#pragma unroll
                for (int off = 1; off <= 2; off <<= 1) {
                    float om = __shfl_xor_sync(0xffffffffu, m, off);
                    float os = __shfl_xor_sync(0xffffffffu, s, off);
                    osm(m, s, om, os);
                }
                if (t == 0) {
                    int row = wm + i * 16 + h * 8 + g;
                    redm[row * 2 + (wid >> 2)] = m;
                    reds[row * 2 + (wid >> 2)] = s;
                }
            }
        __syncthreads();
        if (tid < 128) {
            float m = redm[tid * 2], s = reds[tid * 2];
            osm(m, s, redm[tid * 2 + 1], reds[tid * 2 + 1]);
            g_pmax[tid * NBG + bx] = m;
            g_psum[tid * NBG + bx] = s;
        }
    } else {
        // ---- epilogue: score_c = tanh(rowsum tanh(c+bias)*dh) + mask ----------
        int r0 = (bx - NBG) * 64;
        float rs[2][2] = {{0.f, 0.f}, {0.f, 0.f}};
#pragma unroll
        for (int i = 0; i < 2; i++) {
            int grow = r0 + wm + i * 16 + g;
            int b0r = grow / TT;
            int b1r = (grow + 8) / TT;
#pragma unroll
            for (int j = 0; j < 8; j++) {
                int col = wn + j * 8 + 2 * t;
                float bi0 = cbias[col], bi1 = cbias[col + 1];
                rs[i][0] += tanhf(c[i][j][0] + bi0) * g_dh[b0r * HH + col]
                          + tanhf(c[i][j][1] + bi1) * g_dh[b0r * HH + col + 1];
                rs[i][1] += tanhf(c[i][j][2] + bi0) * g_dh[b1r * HH + col]
                          + tanhf(c[i][j][3] + bi1) * g_dh[b1r * HH + col + 1];
            }
        }
        __syncthreads();
        float* red = (float*)dyn;            // [64][4]
#pragma unroll
        for (int i = 0; i < 2; i++)
#pragma unroll
            for (int h = 0; h < 2; h++) {
                float v = rs[i][h];
                v += __shfl_xor_sync(0xffffffffu, v, 1);
                v += __shfl_xor_sync(0xffffffffu, v, 2);
                if (t == 0) red[(wm + i * 16 + h * 8 + g) * 4 + (wid >> 1)] = v;
            }
        __syncthreads();
        if (tid < 64) {
            float tot = red[tid * 4] + red[tid * 4 + 1] + red[tid * 4 + 2] + red[tid * 4 + 3];
            float v = tanhf(tot);
            int grow = r0 + tid;
            if (idxs[grow] == 0) v -= 10000.f;
            g_scraw[grow] = v;
        }
    }
}

// ---------------- merge partials -> row (M, 1/S) ---------------------------
__global__ void k_merge() {
    int b = blockIdx.x, tid = threadIdx.x;
    __shared__ float sm_[256], ss_[256];
    float m = -1e30f, s = 0.f;
    for (int i = tid; i < NBG; i += 256) osm(m, s, g_pmax[b * NBG + i], g_psum[b * NBG + i]);
    for (int t2 = tid; t2 < TT; t2 += 256) osm(m, s, g_scraw[b * TT + t2], 1.f);
    sm_[tid] = m; ss_[tid] = s; __syncthreads();
    for (int st = 128; st > 0; st >>= 1) {
        if (tid < st) {
            float m2 = sm_[tid], s2 = ss_[tid];
            osm(m2, s2, sm_[tid + st], ss_[tid + st]);
            sm_[tid] = m2; ss_[tid] = s2;
        }
        __syncthreads();
    }
    if (tid == 0) { g_M[b] = sm_[0]; g_invS[b] = 1.f / ss_[0]; }
}

// ---------------- normalize score_g -> out (scalar stores: VO odd) ---------
__global__ void __launch_bounds__(512) k_out(float* __restrict__ out) {
    int b = blockIdx.y, tid = threadIdx.x;
    float M = g_M[b], inv = g_invS[b];
    const __half* sg = g_scoreh + (size_t)b * VVP;
    float* orow = out + (size_t)b * VO;
    int c0 = blockIdx.x * 4096 + tid * 8;
    if (c0 + 7 < VV) {
        const __half2* p = (const __half2*)(sg + c0);
        __half2 q0 = p[0], q1 = p[1], q2 = p[2], q3 = p[3];
        orow[c0 + 0] = __expf(__half2float(__low2half(q0))  - M) * inv;
        orow[c0 + 1] = __expf(__half2float(__high2half(q0)) - M) * inv;
        orow[c0 + 2] = __expf(__half2float(__low2half(q1))  - M) * inv;
        orow[c0 + 3] = __expf(__half2float(__high2half(q1)) - M) * inv;
        orow[c0 + 4] = __expf(__half2float(__low2half(q2))  - M) * inv;
        orow[c0 + 5] = __expf(__half2float(__high2half(q2)) - M) * inv;
        orow[c0 + 6] = __expf(__half2float(__low2half(q3))  - M) * inv;
        orow[c0 + 7] = __expf(__half2float(__high2half(q3)) - M) * inv;
    } else {
        for (int c = c0; c < VV && c < c0 + 8; c++)
            orow[c] = __expf(__half2float(sg[c]) - M) * inv;
    }
}

// ---------------- tail: probc + OOV + scatter + selective_read -------------
__global__ void __launch_bounds__(256) k_tail(
        const int* __restrict__ idxs, const int* __restrict__ dec,
        const float* __restrict__ EO, float* __restrict__ out,
        float* __restrict__ out_sr) {
    __shared__ float pc[TT];
    __shared__ int mt[TT];
    __shared__ int cnt;
    int b = blockIdx.x, tid = threadIdx.x;
    float M = g_M[b], inv = g_invS[b];
    float* orow = out + (size_t)b * VO;
    if (tid == 0) cnt = 0;
    for (int t2 = tid; t2 < TT; t2 += 256)
        pc[t2] = __expf(g_scraw[b * TT + t2] - M) * inv;
    if (tid < NOOV) orow[VV + tid] = 1e-4f;
    __syncthreads();
    int d = dec[b];
    for (int t2 = tid; t2 < TT; t2 += 256) {
        atomicAdd(&orow[idxs[b * TT + t2]], pc[t2]);
        if (idxs[b * TT + t2] == d) { int p = atomicAdd(&cnt, 1); mt[p] = t2; }
    }
    __syncthreads();
    int n = cnt;
    float scale = (n > 1) ? 1.f / (float)n : 1.f;
    for (int e = tid; e < 2 * HH; e += 256) {
        float acc = 0.f;
        for (int k = 0; k < n; k++) {
            int t2 = mt[k];
            acc += pc[t2] * scale * EO[((size_t)b * TT + t2) * (2 * HH) + e];
        }
        out_sr[b * 2 * HH + e] = acc;
    }
}

// ---------------- launch ----------------------------------------------------
extern "C" void kernel_launch(void* const* d_in, const int* in_sizes, int n_in,
                              void* d_out, int out_size) {
    const int*   dec  = (const int*)d_in[0];
    const float* EO   = (const float*)d_in[1];
    const int*   idxs = (const int*)d_in[2];
    const float* prev = (const float*)d_in[3];
    const float* sr   = (const float*)d_in[4];
    int off = (n_in >= 17 && in_sizes[5] == 1) ? 1 : 0;
    const float* emb  = (const float*)d_in[5 + off];
    const float* W_ih = (const float*)d_in[6 + off];
    const float* W_hh = (const float*)d_in[7 + off];
    const float* b_ih = (const float*)d_in[8 + off];
    const float* b_hh = (const float*)d_in[9 + off];
    const float* Wg_w = (const float*)d_in[12 + off];
    const float* Wg_b = (const float*)d_in[13 + off];
    const float* Wc_w = (const float*)d_in[14 + off];
    const float* Wc_b = (const float*)d_in[15 + off];

    float* out    = (float*)d_out;
    float* out_dh = out + (size_t)BB * VO;
    float* out_sr = out_dh + (size_t)BB * HH;

    cudaFuncSetAttribute(k_big,   cudaFuncAttributeMaxDynamicSharedMemorySize, DYN_BIG);
    cudaFuncSetAttribute(k_gates, cudaFuncAttributeMaxDynamicSharedMemorySize, DYN_GATES);

    k_conv<<<1184, 256>>>(Wg_w, Wc_w, EO);
    k_gates<<<12, 256, DYN_GATES>>>(dec, sr, emb, prev, W_ih, b_ih, W_hh, b_hh);
    k_gru<<<BB, HH>>>(prev, out_dh);
    k_big<<<NBG + NBE, 256, DYN_BIG>>>(Wg_b, Wc_b, idxs);
    k_merge<<<BB, 256>>>();
    k_out<<<dim3(13, BB), 512>>>(out);
    k_tail<<<BB, 256>>>(idxs, dec, EO, out, out_sr);
}

// round 11
// speedup vs baseline: 1.0706x; 1.0706x over previous
#include <cuda_runtime.h>
#include <cuda_fp16.h>
#include <math.h>
#include <stdint.h>

#define BB   128
#define TT   200
#define VV   50257
#define VVP  50264          // half row stride, 16B-aligned rows
#define HH   256
#define EE   128
#define NOOV 50
#define G3   768
#define VO   (VV + NOOV)
#define BT   (BB * TT)
#define SPAD 36             // tf32 gates kernel smem stride (words)

#define NBG  393            // score_g tiles 128x128 (first)
#define NBE  400            // enc tiles 64x256

#define STG_G ((128 + 128) * SPAD)   // gates stage words
#define DYN_GATES (2 * STG_G * 4)

// fp16 k_big smem: row stride 40 halfs (80B) -> conflict-free LDSM
#define KS2      40
#define STGB_G   (256 * KS2 * 2)     // 20480 B (128 A + 128 W rows)
#define STGB_E   (320 * KS2 * 2)     // 25600 B (64 A + 256 W rows)
#define DYN_BIG  (2 * STGB_E)        // 51200 B

// ---------------- scratch ----------------------------------------------
__device__ float  g_gi[BB * G3];
__device__ float  g_gh[BB * G3];
__device__ float  g_dh[BB * HH];
__device__ __half g_scoreh[BB * VVP];
__device__ float  g_scraw[BT];
__device__ float  g_pmax[BB * NBG];
__device__ float  g_psum[BB * NBG];
__device__ float  g_M[BB];
__device__ float  g_invS[BB];

// ---------------- helpers ------------------------------------------------
__device__ __forceinline__ void mma8(float* c, const uint32_t* a, const uint32_t* b) {
    asm volatile(
        "mma.sync.aligned.m16n8k8.row.col.f32.tf32.tf32.f32 "
        "{%0,%1,%2,%3}, {%4,%5,%6,%7}, {%8,%9}, {%0,%1,%2,%3};\n"
        : "+f"(c[0]), "+f"(c[1]), "+f"(c[2]), "+f"(c[3])
        : "r"(a[0]), "r"(a[1]), "r"(a[2]), "r"(a[3]), "r"(b[0]), "r"(b[1]));
}
__device__ __forceinline__ void mma16(float* c, const uint32_t* a, const uint32_t* b) {
    asm volatile(
        "mma.sync.aligned.m16n8k16.row.col.f32.f16.f16.f32 "
        "{%0,%1,%2,%3}, {%4,%5,%6,%7}, {%8,%9}, {%0,%1,%2,%3};\n"
        : "+f"(c[0]), "+f"(c[1]), "+f"(c[2]), "+f"(c[3])
        : "r"(a[0]), "r"(a[1]), "r"(a[2]), "r"(a[3]), "r"(b[0]), "r"(b[1]));
}
__device__ __forceinline__ void ldsm4(uint32_t& r0, uint32_t& r1, uint32_t& r2,
                                      uint32_t& r3, uint32_t addr) {
    asm volatile("ldmatrix.sync.aligned.m8n8.x4.shared.b16 {%0,%1,%2,%3}, [%4];\n"
                 : "=r"(r0), "=r"(r1), "=r"(r2), "=r"(r3) : "r"(addr));
}
__device__ __forceinline__ void cpa16(uint32_t saddr, const void* g, int srcsz) {
    asm volatile("cp.async.ca.shared.global [%0], [%1], 16, %2;\n"
                 :: "r"(saddr), "l"(g), "r"(srcsz));
}
__device__ __forceinline__ void cp_commit() { asm volatile("cp.async.commit_group;\n"); }
__device__ __forceinline__ void cp_wait1()  { asm volatile("cp.async.wait_group 1;\n"); }
__device__ __forceinline__ void osm(float& m, float& s, float om, float os) {
    float M = fmaxf(m, om);
    s = s * __expf(m - M) + os * __expf(om - M);
    m = M;
}

// ---------------- fp16 k_big building blocks -------------------------------
// LDG a half-stage worth of fp32 into registers
template <int NB>
__device__ __forceinline__ void ldg_half(float4 (&buf)[NB], int base,
        int nA, const float* __restrict__ A, int lda,
        const float* __restrict__ W, int ldw, int wvalid, int k0, int tid) {
#pragma unroll
    for (int q = 0; q < NB; q++) {
        int idx4 = tid + (base + q) * 256;
        int row = idx4 >> 3, kp = (idx4 & 7) * 4;
        float4 v;
        if (row < nA) v = *(const float4*)(A + (size_t)row * lda + k0 + kp);
        else {
            int wr = row - nA;
            if (wr < wvalid) v = *(const float4*)(W + (size_t)wr * ldw + k0 + kp);
            else             v = make_float4(0.f, 0.f, 0.f, 0.f);
        }
        buf[q] = v;
    }
}
// convert + STS a half-stage into fp16 smem (row stride KS2 halfs)
template <int NB>
__device__ __forceinline__ void sts_half(const float4 (&buf)[NB], int base,
                                         uint32_t s0, int tid) {
#pragma unroll
    for (int q = 0; q < NB; q++) {
        int idx4 = tid + (base + q) * 256;
        int row = idx4 >> 3, kp = (idx4 & 7) * 4;
        __half2 h0 = __floats2half2_rn(buf[q].x, buf[q].y);
        __half2 h1 = __floats2half2_rn(buf[q].z, buf[q].w);
        uint32_t u0 = *(uint32_t*)&h0, u1 = *(uint32_t*)&h1;
        asm volatile("st.shared.v2.b32 [%0], {%1, %2};\n"
                     :: "r"(s0 + (uint32_t)(row * KS2 + kp) * 2), "r"(u0), "r"(u1));
    }
}
// one k16 step of the 32x64 warp tile, with PRECOMPUTED relative addresses:
// addrs: relA[2] then relB[4], relative to stage base; kk adds kk*32 bytes.
__device__ __forceinline__ void compute_k16(uint32_t sb, const uint32_t* relA,
                                            const uint32_t* relB, int kk,
                                            float c[2][8][4]) {
    uint32_t ko = sb + (uint32_t)kk * 32;
    uint32_t a[2][4];
    ldsm4(a[0][0], a[0][1], a[0][2], a[0][3], ko + relA[0]);
    ldsm4(a[1][0], a[1][1], a[1][2], a[1][3], ko + relA[1]);
#pragma unroll
    for (int jj = 0; jj < 4; jj++) {
        uint32_t r[4];
        ldsm4(r[0], r[1], r[2], r[3], ko + relB[jj]);
        uint32_t b0[2] = {r[0], r[2]}, b1[2] = {r[1], r[3]};
#pragma unroll
        for (int i = 0; i < 2; i++) {
            mma16(c[i][jj * 2],     a[i], b0);
            mma16(c[i][jj * 2 + 1], a[i], b1);
        }
    }
}

// ---------------- tf32 warp mma (gates kernel only) -------------------------
__device__ __forceinline__ void warp_mma(const uint32_t* __restrict__ sA,
                                         const uint32_t* __restrict__ sW,
                                         int wm, int wn, int g, int t,
                                         float c[2][8][4]) {
#pragma unroll
    for (int kk = 0; kk < 4; kk++) {
        int kb = kk * 8;
        uint32_t a[2][4];
#pragma unroll
        for (int i = 0; i < 2; i++) {
            int r = wm + i * 16 + g;
            a[i][0] = sA[r * SPAD + kb + t];     a[i][1] = sA[(r + 8) * SPAD + kb + t];
            a[i][2] = sA[r * SPAD + kb + t + 4]; a[i][3] = sA[(r + 8) * SPAD + kb + t + 4];
        }
        uint32_t bf[8][2];
#pragma unroll
        for (int j = 0; j < 8; j++) {
            int n = wn + j * 8 + g;
            bf[j][0] = sW[n * SPAD + kb + t]; bf[j][1] = sW[n * SPAD + kb + t + 4];
        }
#pragma unroll
        for (int i = 0; i < 2; i++)
#pragma unroll
            for (int j = 0; j < 8; j++) mma8(c[i][j], a[i], bf[j]);
    }
}

// ---------------- gates: gi = [sr|emb] @ W_ih^T + b ; gh = prev @ W_hh^T + b
__global__ void __launch_bounds__(256, 2) k_gates(
        const int* __restrict__ dec, const float* __restrict__ sr,
        const float* __restrict__ emb, const float* __restrict__ prev,
        const float* __restrict__ W_ih, const float* __restrict__ b_ih,
        const float* __restrict__ W_hh, const float* __restrict__ b_hh) {
    extern __shared__ uint32_t dyn[];
    uint32_t sbase = (uint32_t)__cvta_generic_to_shared(dyn);
    int tid = threadIdx.x, wid = tid >> 5, lane = tid & 31;
    int g = lane >> 2, t = lane & 3;
    int wm = (wid & 3) * 32, wn = (wid >> 2) * 64;
    int bx = blockIdx.x;
    bool isGi = bx < 6;
    int n0 = (isGi ? bx : bx - 6) * 128;
    int K  = isGi ? 640 : HH;
    int NIT = K / 32;
    const float* W = (isGi ? W_ih : W_hh) + (size_t)n0 * K;
    const float* bias = isGi ? b_ih : b_hh;
    float* C = isGi ? g_gi : g_gh;

    float c[2][8][4];
#pragma unroll
    for (int i = 0; i < 2; i++)
#pragma unroll
        for (int j = 0; j < 8; j++)
#pragma unroll
            for (int q = 0; q < 4; q++) c[i][j][q] = 0.f;

    auto loadA = [&](int stage, int k0) {
        uint32_t s0 = sbase + (uint32_t)stage * (STG_G * 4);
        if (isGi) {
            for (int idx = tid; idx < 1024; idx += 256) {
                int row = idx >> 3, kp = (idx & 7) * 4;
                const float* src;
                if (k0 < 512) src = sr + (size_t)row * 512 + k0 + kp;
                else          src = emb + (size_t)dec[row] * EE + (k0 - 512) + kp;
                cpa16(s0 + (row * SPAD + kp) * 4, src, 16);
            }
        } else {
            for (int idx = tid; idx < 1024; idx += 256) {
                int row = idx >> 3, kp = (idx & 7) * 4;
                cpa16(s0 + (row * SPAD + kp) * 4, prev + (size_t)row * HH + k0 + kp, 16);
            }
        }
        for (int idx = tid; idx < 1024; idx += 256) {
            int row = idx >> 3, kp = (idx & 7) * 4;
            cpa16(s0 + ((128 + row) * SPAD + kp) * 4, W + (size_t)row * K + k0 + kp, 16);
        }
    };

    loadA(0, 0);  cp_commit();
    loadA(1, 32); cp_commit();
    for (int it = 0; it < NIT; it++) {
        cp_wait1();
        __syncthreads();
        const uint32_t* s = dyn + (it & 1) * STG_G;
        warp_mma(s, s + 128 * SPAD, wm, wn, g, t, c);
        __syncthreads();
        if (it + 2 < NIT) loadA(it & 1, (it + 2) * 32);
        cp_commit();
    }
#pragma unroll
    for (int i = 0; i < 2; i++) {
        int r = wm + i * 16 + g;
#pragma unroll
        for (int j = 0; j < 8; j++) {
            int col = n0 + wn + j * 8 + 2 * t;
            float b0 = bias[col], b1 = bias[col + 1];
            C[(size_t)r * G3 + col]           = c[i][j][0] + b0;
            C[(size_t)r * G3 + col + 1]       = c[i][j][1] + b1;
            C[(size_t)(r + 8) * G3 + col]     = c[i][j][2] + b0;
            C[(size_t)(r + 8) * G3 + col + 1] = c[i][j][3] + b1;
        }
    }
}

// ---------------- GRU gate fusion -----------------------------------------
__global__ void k_gru(const float* __restrict__ hprev, float* __restrict__ out_dh) {
    int b = blockIdx.x, j = threadIdx.x;
    const float* gi = g_gi + b * G3;
    const float* gh = g_gh + b * G3;
    float r  = 1.f / (1.f + expf(-(gi[j] + gh[j])));
    float z  = 1.f / (1.f + expf(-(gi[HH+j] + gh[HH+j])));
    float n  = tanhf(gi[2*HH+j] + r * gh[2*HH+j]);
    float h  = hprev[b * HH + j];
    float dh = (1.f - z) * n + z * h;
    g_dh[b*HH+j]   = dh;
    out_dh[b*HH+j] = dh;
}

// ---------------- big fused fp16 tensor-core kernel -------------------------
// bx < NBG : score_g tile 128x128, K=256 ; else : enc tile 64x256, K=512
__global__ void __launch_bounds__(256, 2) k_big(
        const float* __restrict__ Wg, const float* __restrict__ gbias,
        const float* __restrict__ EO, const float* __restrict__ Wc,
        const float* __restrict__ cbias, const int* __restrict__ idxs) {
    extern __shared__ uint32_t dyn[];
    uint32_t sbase = (uint32_t)__cvta_generic_to_shared(dyn);
    int tid = threadIdx.x, wid = tid >> 5, lane = tid & 31;
    int g = lane >> 2, t = lane & 3;
    int bx = blockIdx.x;
    bool isg = bx < NBG;

    // lane-derived ldmatrix offsets (constant per thread)
    int lr = lane & 7;
    int rowadj = ((lane >> 3) & 1) * 8 + lr;
    int kadj = (lane >> 4) * 8;

    float c[2][8][4];
#pragma unroll
    for (int i = 0; i < 2; i++)
#pragma unroll
        for (int j = 0; j < 8; j++)
#pragma unroll
            for (int q = 0; q < 4; q++) c[i][j][q] = 0.f;

    if (isg) {
        // ============ gemmg: 128x128, K=256, NIT=8, fp16 pipeline ============
        int wm = (wid & 3) * 32, wn = (wid >> 2) * 64;
        const float* A = g_dh;   const int lda = HH;   const int nA = 128;
        const float* W = Wg + (size_t)bx * 128 * HH;   const int ldw = HH;
        int wvalid = VV - bx * 128; if (wvalid > 128) wvalid = 128;
        const int NIT = 8;
        uint32_t st0 = sbase, st1 = sbase + STGB_G;
        // precomputed fragment addresses (relative to stage base)
        uint32_t relA[2], relB[4];
#pragma unroll
        for (int i = 0; i < 2; i++)
            relA[i] = (uint32_t)((wm + i * 16 + rowadj) * KS2 + kadj) * 2;
#pragma unroll
        for (int j = 0; j < 4; j++)
            relB[j] = (uint32_t)((nA + wn + j * 16 + rowadj) * KS2 + kadj) * 2;

        float4 buf[4];
        ldg_half<4>(buf, 0, nA, A, lda, W, ldw, wvalid, 0, tid);
        sts_half<4>(buf, 0, st0, tid);
        ldg_half<4>(buf, 4, nA, A, lda, W, ldw, wvalid, 0, tid);
        sts_half<4>(buf, 4, st0, tid);
        __syncthreads();
        for (int it = 0; it < NIT; it++) {
            uint32_t scur = (it & 1) ? st1 : st0;
            uint32_t snxt = (it & 1) ? st0 : st1;
            bool more = (it + 1 < NIT);
            if (more) ldg_half<4>(buf, 0, nA, A, lda, W, ldw, wvalid, (it + 1) * 32, tid);
            compute_k16(scur, relA, relB, 0, c);
            if (more) { sts_half<4>(buf, 0, snxt, tid);
                        ldg_half<4>(buf, 4, nA, A, lda, W, ldw, wvalid, (it + 1) * 32, tid); }
            compute_k16(scur, relA, relB, 1, c);
            if (more) sts_half<4>(buf, 4, snxt, tid);
            __syncthreads();
        }
        // ---- epilogue: half store (+bias) and per-tile online (max, sumexp) --
        int n0 = bx * 128;
        float lm[2][2], ls[2][2];
#pragma unroll
        for (int i = 0; i < 2; i++)
#pragma unroll
            for (int h = 0; h < 2; h++) { lm[i][h] = -1e30f; ls[i][h] = 0.f; }
#pragma unroll
        for (int i = 0; i < 2; i++) {
            int r = wm + i * 16 + g;
#pragma unroll
            for (int j = 0; j < 8; j++) {
                int col = n0 + wn + j * 8 + 2 * t;
                if (col < VV) {
                    bool p1 = (col + 1 < VV);
                    float b0 = gbias[col];
                    float b1 = p1 ? gbias[col + 1] : 0.f;
                    __half2 h02 = __floats2half2_rn(c[i][j][0] + b0, c[i][j][1] + b1);
                    __half2 h23 = __floats2half2_rn(c[i][j][2] + b0, c[i][j][3] + b1);
                    *(__half2*)(g_scoreh + (size_t)r * VVP + col)       = h02;
                    *(__half2*)(g_scoreh + (size_t)(r + 8) * VVP + col) = h23;
                    float w0 = __half2float(__low2half(h02));
                    float w1 = __half2float(__high2half(h02));
                    float w2 = __half2float(__low2half(h23));
                    float w3 = __half2float(__high2half(h23));
                    lm[i][0] = fmaxf(lm[i][0], w0);
                    lm[i][1] = fmaxf(lm[i][1], w2);
                    if (p1) { lm[i][0] = fmaxf(lm[i][0], w1); lm[i][1] = fmaxf(lm[i][1], w3); }
                }
            }
        }
#pragma unroll
        for (int i = 0; i < 2; i++)
#pragma unroll
            for (int j = 0; j < 8; j++) {
                int col = n0 + wn + j * 8 + 2 * t;
                if (col < VV) {
                    bool p1 = (col + 1 < VV);
                    float b0 = gbias[col];
                    float b1 = p1 ? gbias[col + 1] : 0.f;
                    float w0 = __half2float(__float2half_rn(c[i][j][0] + b0));
                    float w2 = __half2float(__float2half_rn(c[i][j][2] + b0));
                    ls[i][0] += __expf(w0 - lm[i][0]);
                    ls[i][1] += __expf(w2 - lm[i][1]);
                    if (p1) {
                        float w1 = __half2float(__float2half_rn(c[i][j][1] + b1));
                        float w3 = __half2float(__float2half_rn(c[i][j][3] + b1));
                        ls[i][0] += __expf(w1 - lm[i][0]);
                        ls[i][1] += __expf(w3 - lm[i][1]);
                    }
                }
            }
        __syncthreads();
        float* redm = (float*)dyn;           // [128][2]
        float* reds = redm + 256;
#pragma unroll
        for (int i = 0; i < 2; i++)
#pragma unroll
            for (int h = 0; h < 2; h++) {
                float m = lm[i][h], s = ls[i][h];
#pragma unroll
                for (int off = 1; off <= 2; off <<= 1) {
                    float om = __shfl_xor_sync(0xffffffffu, m, off);
                    float os = __shfl_xor_sync(0xffffffffu, s, off);
                    osm(m, s, om, os);
                }
                if (t == 0) {
                    int row = wm + i * 16 + h * 8 + g;
                    redm[row * 2 + (wid >> 2)] = m;
                    reds[row * 2 + (wid >> 2)] = s;
                }
            }
        __syncthreads();
        if (tid < 128) {
            float m = redm[tid * 2], s = reds[tid * 2];
            osm(m, s, redm[tid * 2 + 1], reds[tid * 2 + 1]);
            g_pmax[tid * NBG + bx] = m;
            g_psum[tid * NBG + bx] = s;
        }
    } else {
        // ============ enc: 64x256, K=512, NIT=16, fp16 pipeline ==============
        int wm = (wid & 1) * 32, wn = (wid >> 1) * 64;
        int r0 = (bx - NBG) * 64;
        const float* A = EO + (size_t)r0 * (2 * HH);  const int lda = 2 * HH;
        const int nA = 64;
        const float* W = Wc;  const int ldw = 2 * HH; const int wvalid = 256;
        const int NIT = 16;
        uint32_t st0 = sbase, st1 = sbase + STGB_E;
        uint32_t relA[2], relB[4];
#pragma unroll
        for (int i = 0; i < 2; i++)
            relA[i] = (uint32_t)((wm + i * 16 + rowadj) * KS2 + kadj) * 2;
#pragma unroll
        for (int j = 0; j < 4; j++)
            relB[j] = (uint32_t)((nA + wn + j * 16 + rowadj) * KS2 + kadj) * 2;

        float4 buf[5];
        ldg_half<5>(buf, 0, nA, A, lda, W, ldw, wvalid, 0, tid);
        sts_half<5>(buf, 0, st0, tid);
        ldg_half<5>(buf, 5, nA, A, lda, W, ldw, wvalid, 0, tid);
        sts_half<5>(buf, 5, st0, tid);
        __syncthreads();
        for (int it = 0; it < NIT; it++) {
            uint32_t scur = (it & 1) ? st1 : st0;
            uint32_t snxt = (it & 1) ? st0 : st1;
            bool more = (it + 1 < NIT);
            if (more) ldg_half<5>(buf, 0, nA, A, lda, W, ldw, wvalid, (it + 1) * 32, tid);
            compute_k16(scur, relA, relB, 0, c);
            if (more) { sts_half<5>(buf, 0, snxt, tid);
                        ldg_half<5>(buf, 5, nA, A, lda, W, ldw, wvalid, (it + 1) * 32, tid); }
            compute_k16(scur, relA, relB, 1, c);
            if (more) sts_half<5>(buf, 5, snxt, tid);
            __syncthreads();
        }
        // ---- epilogue: score_c = tanh(rowsum tanh(c+bias)*dh) + mask ----------
        float rs[2][2] = {{0.f, 0.f}, {0.f, 0.f}};
#pragma unroll
        for (int i = 0; i < 2; i++) {
            int grow = r0 + wm + i * 16 + g;
            int b0r = grow / TT;
            int b1r = (grow + 8) / TT;
#pragma unroll
            for (int j = 0; j < 8; j++) {
                int col = wn + j * 8 + 2 * t;
                float bi0 = cbias[col], bi1 = cbias[col + 1];
                rs[i][0] += tanhf(c[i][j][0] + bi0) * g_dh[b0r * HH + col]
                          + tanhf(c[i][j][1] + bi1) * g_dh[b0r * HH + col + 1];
                rs[i][1] += tanhf(c[i][j][2] + bi0) * g_dh[b1r * HH + col]
                          + tanhf(c[i][j][3] + bi1) * g_dh[b1r * HH + col + 1];
            }
        }
        __syncthreads();
        float* red = (float*)dyn;            // [64][4]
#pragma unroll
        for (int i = 0; i < 2; i++)
#pragma unroll
            for (int h = 0; h < 2; h++) {
                float v = rs[i][h];
                v += __shfl_xor_sync(0xffffffffu, v, 1);
                v += __shfl_xor_sync(0xffffffffu, v, 2);
                if (t == 0) red[(wm + i * 16 + h * 8 + g) * 4 + (wid >> 1)] = v;
            }
        __syncthreads();
        if (tid < 64) {
            float tot = red[tid * 4] + red[tid * 4 + 1] + red[tid * 4 + 2] + red[tid * 4 + 3];
            float v = tanhf(tot);
            int grow = r0 + tid;
            if (idxs[grow] == 0) v -= 10000.f;
            g_scraw[grow] = v;
        }
    }
}

// ---------------- merge partials -> row (M, 1/S) ---------------------------
__global__ void k_merge() {
    int b = blockIdx.x, tid = threadIdx.x;
    __shared__ float sm_[256], ss_[256];
    float m = -1e30f, s = 0.f;
    for (int i = tid; i < NBG; i += 256) osm(m, s, g_pmax[b * NBG + i], g_psum[b * NBG + i]);
    for (int t2 = tid; t2 < TT; t2 += 256) osm(m, s, g_scraw[b * TT + t2], 1.f);
    sm_[tid] = m; ss_[tid] = s; __syncthreads();
    for (int st = 128; st > 0; st >>= 1) {
        if (tid < st) {
            float m2 = sm_[tid], s2 = ss_[tid];
            osm(m2, s2, sm_[tid + st], ss_[tid + st]);
            sm_[tid] = m2; ss_[tid] = s2;
        }
        __syncthreads();
    }
    if (tid == 0) { g_M[b] = sm_[0]; g_invS[b] = 1.f / ss_[0]; }
}

// ---------------- normalize score_g -> out (scalar stores: VO odd) ---------
__global__ void __launch_bounds__(512) k_out(float* __restrict__ out) {
    int b = blockIdx.y, tid = threadIdx.x;
    float M = g_M[b], inv = g_invS[b];
    const __half* sg = g_scoreh + (size_t)b * VVP;
    float* orow = out + (size_t)b * VO;
    int c0 = blockIdx.x * 4096 + tid * 8;
    if (c0 + 7 < VV) {
        const __half2* p = (const __half2*)(sg + c0);
        __half2 q0 = p[0], q1 = p[1], q2 = p[2], q3 = p[3];
        orow[c0 + 0] = __expf(__half2float(__low2half(q0))  - M) * inv;
        orow[c0 + 1] = __expf(__half2float(__high2half(q0)) - M) * inv;
        orow[c0 + 2] = __expf(__half2float(__low2half(q1))  - M) * inv;
        orow[c0 + 3] = __expf(__half2float(__high2half(q1)) - M) * inv;
        orow[c0 + 4] = __expf(__half2float(__low2half(q2))  - M) * inv;
        orow[c0 + 5] = __expf(__half2float(__high2half(q2)) - M) * inv;
        orow[c0 + 6] = __expf(__half2float(__low2half(q3))  - M) * inv;
        orow[c0 + 7] = __expf(__half2float(__high2half(q3)) - M) * inv;
    } else {
        for (int c = c0; c < VV && c < c0 + 8; c++)
            orow[c] = __expf(__half2float(sg[c]) - M) * inv;
    }
}

// ---------------- tail: probc + OOV + scatter + selective_read -------------
__global__ void __launch_bounds__(256) k_tail(
        const int* __restrict__ idxs, const int* __restrict__ dec,
        const float* __restrict__ EO, float* __restrict__ out,
        float* __restrict__ out_sr) {
    __shared__ float pc[TT];
    __shared__ int mt[TT];
    __shared__ int cnt;
    int b = blockIdx.x, tid = threadIdx.x;
    float M = g_M[b], inv = g_invS[b];
    float* orow = out + (size_t)b * VO;
    if (tid == 0) cnt = 0;
    for (int t2 = tid; t2 < TT; t2 += 256)
        pc[t2] = __expf(g_scraw[b * TT + t2] - M) * inv;
    if (tid < NOOV) orow[VV + tid] = 1e-4f;
    __syncthreads();
    int d = dec[b];
    for (int t2 = tid; t2 < TT; t2 += 256) {
        atomicAdd(&orow[idxs[b * TT + t2]], pc[t2]);
        if (idxs[b * TT + t2] == d) { int p = atomicAdd(&cnt, 1); mt[p] = t2; }
    }
    __syncthreads();
    int n = cnt;
    float scale = (n > 1) ? 1.f / (float)n : 1.f;
    for (int e = tid; e < 2 * HH; e += 256) {
        float acc = 0.f;
        for (int k = 0; k < n; k++) {
            int t2 = mt[k];
            acc += pc[t2] * scale * EO[((size_t)b * TT + t2) * (2 * HH) + e];
        }
        out_sr[b * 2 * HH + e] = acc;
    }
}

// ---------------- launch ----------------------------------------------------
extern "C" void kernel_launch(void* const* d_in, const int* in_sizes, int n_in,
                              void* d_out, int out_size) {
    const int*   dec  = (const int*)d_in[0];
    const float* EO   = (const float*)d_in[1];
    const int*   idxs = (const int*)d_in[2];
    const float* prev = (const float*)d_in[3];
    const float* sr   = (const float*)d_in[4];
    int off = (n_in >= 17 && in_sizes[5] == 1) ? 1 : 0;
    const float* emb  = (const float*)d_in[5 + off];
    const float* W_ih = (const float*)d_in[6 + off];
    const float* W_hh = (const float*)d_in[7 + off];
    const float* b_ih = (const float*)d_in[8 + off];
    const float* b_hh = (const float*)d_in[9 + off];
    const float* Wg_w = (const float*)d_in[12 + off];
    const float* Wg_b = (const float*)d_in[13 + off];
    const float* Wc_w = (const float*)d_in[14 + off];
    const float* Wc_b = (const float*)d_in[15 + off];

    float* out    = (float*)d_out;
    float* out_dh = out + (size_t)BB * VO;
    float* out_sr = out_dh + (size_t)BB * HH;

    cudaFuncSetAttribute(k_big,   cudaFuncAttributeMaxDynamicSharedMemorySize, DYN_BIG);
    cudaFuncSetAttribute(k_gates, cudaFuncAttributeMaxDynamicSharedMemorySize, DYN_GATES);

    k_gates<<<12, 256, DYN_GATES>>>(dec, sr, emb, prev, W_ih, b_ih, W_hh, b_hh);
    k_gru<<<BB, HH>>>(prev, out_dh);
    k_big<<<NBG + NBE, 256, DYN_BIG>>>(Wg_w, Wg_b, EO, Wc_w, Wc_b, idxs);
    k_merge<<<BB, 256>>>();
    k_out<<<dim3(13, BB), 512>>>(out);
    k_tail<<<BB, 256>>>(idxs, dec, EO, out, out_sr);
}

// round 13
// speedup vs baseline: 1.1191x; 1.0453x over previous
#include <cuda_runtime.h>
#include <cuda_fp16.h>
#include <math.h>
#include <stdint.h>

#define BB   128
#define TT   200
#define VV   50257
#define VVP  50264          // half row stride, 16B-aligned rows
#define HH   256
#define EE   128
#define NOOV 50
#define G3   768
#define VO   (VV + NOOV)
#define BT   (BB * TT)
#define SPAD 36             // tf32 gates smem stride (words)

#define NBG  393            // score_g tiles 128x128
#define NBE  400            // enc tiles 64x256

// fused-kernel block layout
#define OFF_GATES 0
#define OFF_GRU   12
#define OFF_ENC   140
#define OFF_GEMG  (OFF_ENC + NBE)      // 540
#define OFF_MERGE (OFF_GEMG + NBG)     // 933
#define NBLK      (OFF_MERGE + BB)     // 1061

#define STG_G ((128 + 128) * SPAD)     // gates stage words
#define DYN_FUSED (2 * STG_G * 4)      // 73728 B (covers fp16 stages 51200 too)

// fp16 mma smem: row stride 40 halfs (80B) -> conflict-free LDSM
#define KS2      40
#define STGB_G   (256 * KS2 * 2)       // 20480 B
#define STGB_E   (320 * KS2 * 2)       // 25600 B

// ---------------- scratch ----------------------------------------------
__device__ float  g_gi[BB * G3];
__device__ float  g_gh[BB * G3];
__device__ float  g_dh[BB * HH];
__device__ __half g_scoreh[BB * VVP];
__device__ float  g_scraw[BT];
__device__ float  g_pmax[BB * NBG];
__device__ float  g_psum[BB * NBG];
__device__ float  g_M[BB];
__device__ float  g_invS[BB];
__device__ int    g_c_gates;   // zero-init; reset each replay by k_tail
__device__ int    g_c_gru;
__device__ int    g_c_tiles;

// ---------------- helpers ------------------------------------------------
__device__ __forceinline__ void mma8(float* c, const uint32_t* a, const uint32_t* b) {
    asm volatile(
        "mma.sync.aligned.m16n8k8.row.col.f32.tf32.tf32.f32 "
        "{%0,%1,%2,%3}, {%4,%5,%6,%7}, {%8,%9}, {%0,%1,%2,%3};\n"
        : "+f"(c[0]), "+f"(c[1]), "+f"(c[2]), "+f"(c[3])
        : "r"(a[0]), "r"(a[1]), "r"(a[2]), "r"(a[3]), "r"(b[0]), "r"(b[1]));
}
__device__ __forceinline__ void mma16(float* c, const uint32_t* a, const uint32_t* b) {
    asm volatile(
        "mma.sync.aligned.m16n8k16.row.col.f32.f16.f16.f32 "
        "{%0,%1,%2,%3}, {%4,%5,%6,%7}, {%8,%9}, {%0,%1,%2,%3};\n"
        : "+f"(c[0]), "+f"(c[1]), "+f"(c[2]), "+f"(c[3])
        : "r"(a[0]), "r"(a[1]), "r"(a[2]), "r"(a[3]), "r"(b[0]), "r"(b[1]));
}
__device__ __forceinline__ void ldsm4(uint32_t& r0, uint32_t& r1, uint32_t& r2,
                                      uint32_t& r3, uint32_t addr) {
    asm volatile("ldmatrix.sync.aligned.m8n8.x4.shared.b16 {%0,%1,%2,%3}, [%4];\n"
                 : "=r"(r0), "=r"(r1), "=r"(r2), "=r"(r3) : "r"(addr));
}
__device__ __forceinline__ void cpa16(uint32_t saddr, const void* g, int srcsz) {
    asm volatile("cp.async.ca.shared.global [%0], [%1], 16, %2;\n"
                 :: "r"(saddr), "l"(g), "r"(srcsz));
}
__device__ __forceinline__ void cp_commit() { asm volatile("cp.async.commit_group;\n"); }
__device__ __forceinline__ void cp_wait1()  { asm volatile("cp.async.wait_group 1;\n"); }
__device__ __forceinline__ void osm(float& m, float& s, float om, float os) {
    float M = fmaxf(m, om);
    s = s * __expf(m - M) + os * __expf(om - M);
    m = M;
}
// block done: all threads fence, then tid0 bumps counter
__device__ __forceinline__ void mark_done(int* ctr) {
    __threadfence();
    __syncthreads();
    if (threadIdx.x == 0) atomicAdd(ctr, 1);
}
// block wait: tid0 spins until counter >= target
__device__ __forceinline__ void spin_ge(int* ctr, int target) {
    if (threadIdx.x == 0) {
        while (atomicAdd(ctr, 0) < target) __nanosleep(64);
    }
    __syncthreads();
    __threadfence();
}

// ---------------- fp16 mma building blocks ---------------------------------
template <int NB>
__device__ __forceinline__ void ldg_half(float4 (&buf)[NB], int base,
        int nA, const float* __restrict__ A, int lda,
        const float* __restrict__ W, int ldw, int wvalid, int k0, int tid) {
#pragma unroll
    for (int q = 0; q < NB; q++) {
        int idx4 = tid + (base + q) * 256;
        int row = idx4 >> 3, kp = (idx4 & 7) * 4;
        float4 v;
        if (row < nA) v = *(const float4*)(A + (size_t)row * lda + k0 + kp);
        else {
            int wr = row - nA;
            if (wr < wvalid) v = *(const float4*)(W + (size_t)wr * ldw + k0 + kp);
            else             v = make_float4(0.f, 0.f, 0.f, 0.f);
        }
        buf[q] = v;
    }
}
template <int NB>
__device__ __forceinline__ void sts_half(const float4 (&buf)[NB], int base,
                                         uint32_t s0, int tid) {
#pragma unroll
    for (int q = 0; q < NB; q++) {
        int idx4 = tid + (base + q) * 256;
        int row = idx4 >> 3, kp = (idx4 & 7) * 4;
        __half2 h0 = __floats2half2_rn(buf[q].x, buf[q].y);
        __half2 h1 = __floats2half2_rn(buf[q].z, buf[q].w);
        uint32_t u0 = *(uint32_t*)&h0, u1 = *(uint32_t*)&h1;
        asm volatile("st.shared.v2.b32 [%0], {%1, %2};\n"
                     :: "r"(s0 + (uint32_t)(row * KS2 + kp) * 2), "r"(u0), "r"(u1));
    }
}
__device__ __forceinline__ void compute_k16(uint32_t sb, const uint32_t* relA,
                                            const uint32_t* relB, int kk,
                                            float c[2][8][4]) {
    uint32_t ko = sb + (uint32_t)kk * 32;
    uint32_t a[2][4];
    ldsm4(a[0][0], a[0][1], a[0][2], a[0][3], ko + relA[0]);
    ldsm4(a[1][0], a[1][1], a[1][2], a[1][3], ko + relA[1]);
#pragma unroll
    for (int jj = 0; jj < 4; jj++) {
        uint32_t r[4];
        ldsm4(r[0], r[1], r[2], r[3], ko + relB[jj]);
        uint32_t b0[2] = {r[0], r[2]}, b1[2] = {r[1], r[3]};
#pragma unroll
        for (int i = 0; i < 2; i++) {
            mma16(c[i][jj * 2],     a[i], b0);
            mma16(c[i][jj * 2 + 1], a[i], b1);
        }
    }
}

// ---------------- tf32 warp mma (gates role) --------------------------------
__device__ __forceinline__ void warp_mma(const uint32_t* __restrict__ sA,
                                         const uint32_t* __restrict__ sW,
                                         int wm, int wn, int g, int t,
                                         float c[2][8][4]) {
#pragma unroll
    for (int kk = 0; kk < 4; kk++) {
        int kb = kk * 8;
        uint32_t a[2][4];
#pragma unroll
        for (int i = 0; i < 2; i++) {
            int r = wm + i * 16 + g;
            a[i][0] = sA[r * SPAD + kb + t];     a[i][1] = sA[(r + 8) * SPAD + kb + t];
            a[i][2] = sA[r * SPAD + kb + t + 4]; a[i][3] = sA[(r + 8) * SPAD + kb + t + 4];
        }
        uint32_t bf[8][2];
#pragma unroll
        for (int j = 0; j < 8; j++) {
            int n = wn + j * 8 + g;
            bf[j][0] = sW[n * SPAD + kb + t]; bf[j][1] = sW[n * SPAD + kb + t + 4];
        }
#pragma unroll
        for (int i = 0; i < 2; i++)
#pragma unroll
            for (int j = 0; j < 8; j++) mma8(c[i][j], a[i], bf[j]);
    }
}

// ---------------- roles ------------------------------------------------------
__device__ void role_gates(uint32_t* dyn, int bx,
        const int* __restrict__ dec, const float* __restrict__ sr,
        const float* __restrict__ emb, const float* __restrict__ prev,
        const float* __restrict__ W_ih, const float* __restrict__ b_ih,
        const float* __restrict__ W_hh, const float* __restrict__ b_hh) {
    uint32_t sbase = (uint32_t)__cvta_generic_to_shared(dyn);
    int tid = threadIdx.x, wid = tid >> 5, lane = tid & 31;
    int g = lane >> 2, t = lane & 3;
    int wm = (wid & 3) * 32, wn = (wid >> 2) * 64;
    bool isGi = bx < 6;
    int n0 = (isGi ? bx : bx - 6) * 128;
    int K  = isGi ? 640 : HH;
    int NIT = K / 32;
    const float* W = (isGi ? W_ih : W_hh) + (size_t)n0 * K;
    const float* bias = isGi ? b_ih : b_hh;
    float* C = isGi ? g_gi : g_gh;

    float c[2][8][4];
#pragma unroll
    for (int i = 0; i < 2; i++)
#pragma unroll
        for (int j = 0; j < 8; j++)
#pragma unroll
            for (int q = 0; q < 4; q++) c[i][j][q] = 0.f;

    auto loadA = [&](int stage, int k0) {
        uint32_t s0 = sbase + (uint32_t)stage * (STG_G * 4);
        if (isGi) {
            for (int idx = tid; idx < 1024; idx += 256) {
                int row = idx >> 3, kp = (idx & 7) * 4;
                const float* src;
                if (k0 < 512) src = sr + (size_t)row * 512 + k0 + kp;
                else          src = emb + (size_t)dec[row] * EE + (k0 - 512) + kp;
                cpa16(s0 + (row * SPAD + kp) * 4, src, 16);
            }
        } else {
            for (int idx = tid; idx < 1024; idx += 256) {
                int row = idx >> 3, kp = (idx & 7) * 4;
                cpa16(s0 + (row * SPAD + kp) * 4, prev + (size_t)row * HH + k0 + kp, 16);
            }
        }
        for (int idx = tid; idx < 1024; idx += 256) {
            int row = idx >> 3, kp = (idx & 7) * 4;
            cpa16(s0 + ((128 + row) * SPAD + kp) * 4, W + (size_t)row * K + k0 + kp, 16);
        }
    };

    loadA(0, 0);  cp_commit();
    loadA(1, 32); cp_commit();
    for (int it = 0; it < NIT; it++) {
        cp_wait1();
        __syncthreads();
        const uint32_t* s = dyn + (it & 1) * STG_G;
        warp_mma(s, s + 128 * SPAD, wm, wn, g, t, c);
        __syncthreads();
        if (it + 2 < NIT) loadA(it & 1, (it + 2) * 32);
        cp_commit();
    }
#pragma unroll
    for (int i = 0; i < 2; i++) {
        int r = wm + i * 16 + g;
#pragma unroll
        for (int j = 0; j < 8; j++) {
            int col = n0 + wn + j * 8 + 2 * t;
            float b0 = bias[col], b1 = bias[col + 1];
            C[(size_t)r * G3 + col]           = c[i][j][0] + b0;
            C[(size_t)r * G3 + col + 1]       = c[i][j][1] + b1;
            C[(size_t)(r + 8) * G3 + col]     = c[i][j][2] + b0;
            C[(size_t)(r + 8) * G3 + col + 1] = c[i][j][3] + b1;
        }
    }
    mark_done(&g_c_gates);
}

__device__ void role_gru(int b, const float* __restrict__ hprev,
                         float* __restrict__ out_dh) {
    spin_ge(&g_c_gates, 12);
    int j = threadIdx.x;
    const float* gi = g_gi + b * G3;
    const float* gh = g_gh + b * G3;
    float r  = 1.f / (1.f + expf(-(gi[j] + gh[j])));
    float z  = 1.f / (1.f + expf(-(gi[HH+j] + gh[HH+j])));
    float n  = tanhf(gi[2*HH+j] + r * gh[2*HH+j]);
    float h  = hprev[b * HH + j];
    float dh = (1.f - z) * n + z * h;
    g_dh[b*HH+j]   = dh;
    out_dh[b*HH+j] = dh;
    mark_done(&g_c_gru);
}

__device__ void role_merge(int b) {
    extern __shared__ uint32_t dyn[];
    float* sm_ = (float*)dyn;
    float* ss_ = sm_ + 256;
    spin_ge(&g_c_tiles, NBE + NBG);
    int tid = threadIdx.x;
    float m = -1e30f, s = 0.f;
    for (int i = tid; i < NBG; i += 256) osm(m, s, g_pmax[b * NBG + i], g_psum[b * NBG + i]);
    for (int t2 = tid; t2 < TT; t2 += 256) osm(m, s, g_scraw[b * TT + t2], 1.f);
    sm_[tid] = m; ss_[tid] = s; __syncthreads();
    for (int st = 128; st > 0; st >>= 1) {
        if (tid < st) {
            float m2 = sm_[tid], s2 = ss_[tid];
            osm(m2, s2, sm_[tid + st], ss_[tid + st]);
            sm_[tid] = m2; ss_[tid] = s2;
        }
        __syncthreads();
    }
    if (tid == 0) { g_M[b] = sm_[0]; g_invS[b] = 1.f / ss_[0]; }
}

// ---------------- fused kernel -----------------------------------------------
__global__ void __launch_bounds__(256, 2) k_fused(
        const int* __restrict__ dec, const float* __restrict__ sr,
        const float* __restrict__ emb, const float* __restrict__ prev,
        const float* __restrict__ W_ih, const float* __restrict__ b_ih,
        const float* __restrict__ W_hh, const float* __restrict__ b_hh,
        const float* __restrict__ Wg, const float* __restrict__ gbias,
        const float* __restrict__ EO, const float* __restrict__ Wc,
        const float* __restrict__ cbias, const int* __restrict__ idxs,
        float* __restrict__ out_dh) {
    extern __shared__ uint32_t dyn[];
    int bid = blockIdx.x;
    if (bid < OFF_GRU) { role_gates(dyn, bid, dec, sr, emb, prev, W_ih, b_ih, W_hh, b_hh); return; }
    if (bid < OFF_ENC) { role_gru(bid - OFF_GRU, prev, out_dh); return; }
    if (bid >= OFF_MERGE) { role_merge(bid - OFF_MERGE); return; }

    // ---- GEMM tiles (enc / gemmg), fp16 mma.sync pipeline (R11-proven) ------
    uint32_t sbase = (uint32_t)__cvta_generic_to_shared(dyn);
    int tid = threadIdx.x, wid = tid >> 5, lane = tid & 31;
    int g = lane >> 2, t = lane & 3;
    bool isg = bid >= OFF_GEMG;

    int lr = lane & 7;
    int rowadj = ((lane >> 3) & 1) * 8 + lr;
    int kadj = (lane >> 4) * 8;

    float c[2][8][4];
#pragma unroll
    for (int i = 0; i < 2; i++)
#pragma unroll
        for (int j = 0; j < 8; j++)
#pragma unroll
            for (int q = 0; q < 4; q++) c[i][j][q] = 0.f;

    if (isg) {
        // ============ gemmg: 128x128, K=256, NIT=8 =========================
        int bx = bid - OFF_GEMG;
        spin_ge(&g_c_gru, BB);                       // A = g_dh must be ready
        int wm = (wid & 3) * 32, wn = (wid >> 2) * 64;
        const float* A = g_dh;   const int lda = HH;   const int nA = 128;
        const float* W = Wg + (size_t)bx * 128 * HH;   const int ldw = HH;
        int wvalid = VV - bx * 128; if (wvalid > 128) wvalid = 128;
        const int NIT = 8;
        uint32_t st0 = sbase, st1 = sbase + STGB_G;
        uint32_t relA[2], relB[4];
#pragma unroll
        for (int i = 0; i < 2; i++)
            relA[i] = (uint32_t)((wm + i * 16 + rowadj) * KS2 + kadj) * 2;
#pragma unroll
        for (int j = 0; j < 4; j++)
            relB[j] = (uint32_t)((nA + wn + j * 16 + rowadj) * KS2 + kadj) * 2;

        float4 buf[4];
        ldg_half<4>(buf, 0, nA, A, lda, W, ldw, wvalid, 0, tid);
        sts_half<4>(buf, 0, st0, tid);
        ldg_half<4>(buf, 4, nA, A, lda, W, ldw, wvalid, 0, tid);
        sts_half<4>(buf, 4, st0, tid);
        __syncthreads();
        for (int it = 0; it < NIT; it++) {
            uint32_t scur = (it & 1) ? st1 : st0;
            uint32_t snxt = (it & 1) ? st0 : st1;
            bool more = (it + 1 < NIT);
            if (more) ldg_half<4>(buf, 0, nA, A, lda, W, ldw, wvalid, (it + 1) * 32, tid);
            compute_k16(scur, relA, relB, 0, c);
            if (more) { sts_half<4>(buf, 0, snxt, tid);
                        ldg_half<4>(buf, 4, nA, A, lda, W, ldw, wvalid, (it + 1) * 32, tid); }
            compute_k16(scur, relA, relB, 1, c);
            if (more) sts_half<4>(buf, 4, snxt, tid);
            __syncthreads();
        }
        // epilogue: half store (+bias) and per-tile online (max, sumexp)
        int n0 = bx * 128;
        float lm[2][2], ls[2][2];
#pragma unroll
        for (int i = 0; i < 2; i++)
#pragma unroll
            for (int h = 0; h < 2; h++) { lm[i][h] = -1e30f; ls[i][h] = 0.f; }
#pragma unroll
        for (int i = 0; i < 2; i++) {
            int r = wm + i * 16 + g;
#pragma unroll
            for (int j = 0; j < 8; j++) {
                int col = n0 + wn + j * 8 + 2 * t;
                if (col < VV) {
                    bool p1 = (col + 1 < VV);
                    float b0 = gbias[col];
                    float b1 = p1 ? gbias[col + 1] : 0.f;
                    __half2 h02 = __floats2half2_rn(c[i][j][0] + b0, c[i][j][1] + b1);
                    __half2 h23 = __floats2half2_rn(c[i][j][2] + b0, c[i][j][3] + b1);
                    *(__half2*)(g_scoreh + (size_t)r * VVP + col)       = h02;
                    *(__half2*)(g_scoreh + (size_t)(r + 8) * VVP + col) = h23;
                    float w0 = __half2float(__low2half(h02));
                    float w1 = __half2float(__high2half(h02));
                    float w2 = __half2float(__low2half(h23));
                    float w3 = __half2float(__high2half(h23));
                    lm[i][0] = fmaxf(lm[i][0], w0);
                    lm[i][1] = fmaxf(lm[i][1], w2);
                    if (p1) { lm[i][0] = fmaxf(lm[i][0], w1); lm[i][1] = fmaxf(lm[i][1], w3); }
                }
            }
        }
#pragma unroll
        for (int i = 0; i < 2; i++)
#pragma unroll
            for (int j = 0; j < 8; j++) {
                int col = n0 + wn + j * 8 + 2 * t;
                if (col < VV) {
                    bool p1 = (col + 1 < VV);
                    float b0 = gbias[col];
                    float b1 = p1 ? gbias[col + 1] : 0.f;
                    float w0 = __half2float(__float2half_rn(c[i][j][0] + b0));
                    float w2 = __half2float(__float2half_rn(c[i][j][2] + b0));
                    ls[i][0] += __expf(w0 - lm[i][0]);
                    ls[i][1] += __expf(w2 - lm[i][1]);
                    if (p1) {
                        float w1 = __half2float(__float2half_rn(c[i][j][1] + b1));
                        float w3 = __half2float(__float2half_rn(c[i][j][3] + b1));
                        ls[i][0] += __expf(w1 - lm[i][0]);
                        ls[i][1] += __expf(w3 - lm[i][1]);
                    }
                }
            }
        __syncthreads();
        float* redm = (float*)dyn;
        float* reds = redm + 256;
#pragma unroll
        for (int i = 0; i < 2; i++)
#pragma unroll
            for (int h = 0; h < 2; h++) {
                float m = lm[i][h], s = ls[i][h];
#pragma unroll
                for (int off = 1; off <= 2; off <<= 1) {
                    float om = __shfl_xor_sync(0xffffffffu, m, off);
                    float os = __shfl_xor_sync(0xffffffffu, s, off);
                    osm(m, s, om, os);
                }
                if (t == 0) {
                    int row = wm + i * 16 + h * 8 + g;
                    redm[row * 2 + (wid >> 2)] = m;
                    reds[row * 2 + (wid >> 2)] = s;
                }
            }
        __syncthreads();
        if (tid < 128) {
            float m = redm[tid * 2], s = reds[tid * 2];
            osm(m, s, redm[tid * 2 + 1], reds[tid * 2 + 1]);
            g_pmax[tid * NBG + bx] = m;
            g_psum[tid * NBG + bx] = s;
        }
        mark_done(&g_c_tiles);
    } else {
        // ============ enc: 64x256, K=512, NIT=16 ============================
        int bx = bid - OFF_ENC;
        int wm = (wid & 1) * 32, wn = (wid >> 1) * 64;
        int r0 = bx * 64;
        const float* A = EO + (size_t)r0 * (2 * HH);  const int lda = 2 * HH;
        const int nA = 64;
        const float* W = Wc;  const int ldw = 2 * HH; const int wvalid = 256;
        const int NIT = 16;
        uint32_t st0 = sbase, st1 = sbase + STGB_E;
        uint32_t relA[2], relB[4];
#pragma unroll
        for (int i = 0; i < 2; i++)
            relA[i] = (uint32_t)((wm + i * 16 + rowadj) * KS2 + kadj) * 2;
#pragma unroll
        for (int j = 0; j < 4; j++)
            relB[j] = (uint32_t)((nA + wn + j * 16 + rowadj) * KS2 + kadj) * 2;

        float4 buf[5];
        ldg_half<5>(buf, 0, nA, A, lda, W, ldw, wvalid, 0, tid);
        sts_half<5>(buf, 0, st0, tid);
        ldg_half<5>(buf, 5, nA, A, lda, W, ldw, wvalid, 0, tid);
        sts_half<5>(buf, 5, st0, tid);
        __syncthreads();
        for (int it = 0; it < NIT; it++) {
            uint32_t scur = (it & 1) ? st1 : st0;
            uint32_t snxt = (it & 1) ? st0 : st1;
            bool more = (it + 1 < NIT);
            if (more) ldg_half<5>(buf, 0, nA, A, lda, W, ldw, wvalid, (it + 1) * 32, tid);
            compute_k16(scur, relA, relB, 0, c);
            if (more) { sts_half<5>(buf, 0, snxt, tid);
                        ldg_half<5>(buf, 5, nA, A, lda, W, ldw, wvalid, (it + 1) * 32, tid); }
            compute_k16(scur, relA, relB, 1, c);
            if (more) sts_half<5>(buf, 5, snxt, tid);
            __syncthreads();
        }
        // epilogue needs dh
        spin_ge(&g_c_gru, BB);
        float rs[2][2] = {{0.f, 0.f}, {0.f, 0.f}};
#pragma unroll
        for (int i = 0; i < 2; i++) {
            int grow = r0 + wm + i * 16 + g;
            int b0r = grow / TT;
            int b1r = (grow + 8) / TT;
#pragma unroll
            for (int j = 0; j < 8; j++) {
                int col = wn + j * 8 + 2 * t;
                float bi0 = cbias[col], bi1 = cbias[col + 1];
                rs[i][0] += tanhf(c[i][j][0] + bi0) * g_dh[b0r * HH + col]
                          + tanhf(c[i][j][1] + bi1) * g_dh[b0r * HH + col + 1];
                rs[i][1] += tanhf(c[i][j][2] + bi0) * g_dh[b1r * HH + col]
                          + tanhf(c[i][j][3] + bi1) * g_dh[b1r * HH + col + 1];
            }
        }
        __syncthreads();
        float* red = (float*)dyn;
#pragma unroll
        for (int i = 0; i < 2; i++)
#pragma unroll
            for (int h = 0; h < 2; h++) {
                float v = rs[i][h];
                v += __shfl_xor_sync(0xffffffffu, v, 1);
                v += __shfl_xor_sync(0xffffffffu, v, 2);
                if (t == 0) red[(wm + i * 16 + h * 8 + g) * 4 + (wid >> 1)] = v;
            }
        __syncthreads();
        if (tid < 64) {
            float tot = red[tid * 4] + red[tid * 4 + 1] + red[tid * 4 + 2] + red[tid * 4 + 3];
            float v = tanhf(tot);
            int grow = r0 + tid;
            if (idxs[grow] == 0) v -= 10000.f;
            g_scraw[grow] = v;
        }
        mark_done(&g_c_tiles);
    }
}

// ---------------- normalize score_g -> out (scalar stores: VO odd) ---------
__global__ void __launch_bounds__(512) k_out(float* __restrict__ out) {
    int b = blockIdx.y, tid = threadIdx.x;
    float M = g_M[b], inv = g_invS[b];
    const __half* sg = g_scoreh + (size_t)b * VVP;
    float* orow = out + (size_t)b * VO;
    int c0 = blockIdx.x * 4096 + tid * 8;
    if (c0 + 7 < VV) {
        const __half2* p = (const __half2*)(sg + c0);
        __half2 q0 = p[0], q1 = p[1], q2 = p[2], q3 = p[3];
        orow[c0 + 0] = __expf(__half2float(__low2half(q0))  - M) * inv;
        orow[c0 + 1] = __expf(__half2float(__high2half(q0)) - M) * inv;
        orow[c0 + 2] = __expf(__half2float(__low2half(q1))  - M) * inv;
        orow[c0 + 3] = __expf(__half2float(__high2half(q1)) - M) * inv;
        orow[c0 + 4] = __expf(__half2float(__low2half(q2))  - M) * inv;
        orow[c0 + 5] = __expf(__half2float(__high2half(q2)) - M) * inv;
        orow[c0 + 6] = __expf(__half2float(__low2half(q3))  - M) * inv;
        orow[c0 + 7] = __expf(__half2float(__high2half(q3)) - M) * inv;
    } else {
        for (int c = c0; c < VV && c < c0 + 8; c++)
            orow[c] = __expf(__half2float(sg[c]) - M) * inv;
    }
}

// ---------------- tail: probc + OOV + scatter + selective_read + reset -----
__global__ void __launch_bounds__(256) k_tail(
        const int* __restrict__ idxs, const int* __restrict__ dec,
        const float* __restrict__ EO, float* __restrict__ out,
        float* __restrict__ out_sr) {
    __shared__ float pc[TT];
    __shared__ int mt[TT];
    __shared__ int cnt;
    int b = blockIdx.x, tid = threadIdx.x;
    if (b == 0 && tid == 0) {        // reset fusion counters for next replay
        g_c_gates = 0; g_c_gru = 0; g_c_tiles = 0;
    }
    float M = g_M[b], inv = g_invS[b];
    float* orow = out + (size_t)b * VO;
    if (tid == 0) cnt = 0;
    for (int t2 = tid; t2 < TT; t2 += 256)
        pc[t2] = __expf(g_scraw[b * TT + t2] - M) * inv;
    if (tid < NOOV) orow[VV + tid] = 1e-4f;
    __syncthreads();
    int d = dec[b];
    for (int t2 = tid; t2 < TT; t2 += 256) {
        atomicAdd(&orow[idxs[b * TT + t2]], pc[t2]);
        if (idxs[b * TT + t2] == d) { int p = atomicAdd(&cnt, 1); mt[p] = t2; }
    }
    __syncthreads();
    int n = cnt;
    float scale = (n > 1) ? 1.f / (float)n : 1.f;
    for (int e = tid; e < 2 * HH; e += 256) {
        float acc = 0.f;
        for (int k = 0; k < n; k++) {
            int t2 = mt[k];
            acc += pc[t2] * scale * EO[((size_t)b * TT + t2) * (2 * HH) + e];
        }
        out_sr[b * 2 * HH + e] = acc;
    }
}

// ---------------- launch ----------------------------------------------------
extern "C" void kernel_launch(void* const* d_in, const int* in_sizes, int n_in,
                              void* d_out, int out_size) {
    const int*   dec  = (const int*)d_in[0];
    const float* EO   = (const float*)d_in[1];
    const int*   idxs = (const int*)d_in[2];
    const float* prev = (const float*)d_in[3];
    const float* sr   = (const float*)d_in[4];
    int off = (n_in >= 17 && in_sizes[5] == 1) ? 1 : 0;
    const float* emb  = (const float*)d_in[5 + off];
    const float* W_ih = (const float*)d_in[6 + off];
    const float* W_hh = (const float*)d_in[7 + off];
    const float* b_ih = (const float*)d_in[8 + off];
    const float* b_hh = (const float*)d_in[9 + off];
    const float* Wg_w = (const float*)d_in[12 + off];
    const float* Wg_b = (const float*)d_in[13 + off];
    const float* Wc_w = (const float*)d_in[14 + off];
    const float* Wc_b = (const float*)d_in[15 + off];

    float* out    = (float*)d_out;
    float* out_dh = out + (size_t)BB * VO;
    float* out_sr = out_dh + (size_t)BB * HH;

    cudaFuncSetAttribute(k_fused, cudaFuncAttributeMaxDynamicSharedMemorySize, DYN_FUSED);

    k_fused<<<NBLK, 256, DYN_FUSED>>>(dec, sr, emb, prev, W_ih, b_ih, W_hh, b_hh,
                                      Wg_w, Wg_b, EO, Wc_w, Wc_b, idxs, out_dh);
    k_out<<<dim3(13, BB), 512>>>(out);
    k_tail<<<BB, 256>>>(idxs, dec, EO, out, out_sr);
}

// round 14
// speedup vs baseline: 1.1757x; 1.0506x over previous
#include <cuda_runtime.h>
#include <cuda_fp16.h>
#include <math.h>
#include <stdint.h>

#define BB   128
#define TT   200
#define VV   50257
#define VVP  50264          // half row stride, 16B-aligned rows
#define HH   256
#define EE   128
#define NOOV 50
#define G3   768
#define VO   (VV + NOOV)
#define BT   (BB * TT)
#define SPAD 36             // tf32 gates smem stride (words)

#define NBG  393            // score_g tiles 128x128
#define NBE  400            // enc tiles 64x256
#define NOUT (13 * BB)      // out segments: 13 x 4096 cols per batch row

// fused-kernel block layout (dependencies always point to lower bids)
#define OFF_GATES 0
#define OFF_GRU   12
#define OFF_ENC   140
#define OFF_GEMG  (OFF_ENC + NBE)      // 540
#define OFF_MERGE (OFF_GEMG + NBG)     // 933
#define OFF_OUT   (OFF_MERGE + BB)     // 1061
#define OFF_TAIL  (OFF_OUT + NOUT)     // 2725
#define NBLK      (OFF_TAIL + BB)      // 2853

#define STG_G ((128 + 128) * SPAD)     // gates stage words
#define DYN_FUSED (2 * STG_G * 4)      // 73728 B

// fp16 mma smem: row stride 40 halfs (80B) -> conflict-free LDSM
#define KS2      40
#define STGB_G   (256 * KS2 * 2)       // 20480 B
#define STGB_E   (320 * KS2 * 2)       // 25600 B

// ---------------- scratch ----------------------------------------------
__device__ float  g_gi[BB * G3];
__device__ float  g_gh[BB * G3];
__device__ float  g_dh[BB * HH];
__device__ __half g_scoreh[BB * VVP];
__device__ float  g_scraw[BT];
__device__ float  g_pmax[BB * NBG];
__device__ float  g_psum[BB * NBG];
__device__ float  g_M[BB];
__device__ float  g_invS[BB];
__device__ int    g_c_gates;   // zero-init; reset by last tail block
__device__ int    g_c_gru;
__device__ int    g_c_tiles;
__device__ int    g_c_merge;
__device__ int    g_c_out;
__device__ int    g_c_tail;

// ---------------- helpers ------------------------------------------------
__device__ __forceinline__ void mma8(float* c, const uint32_t* a, const uint32_t* b) {
    asm volatile(
        "mma.sync.aligned.m16n8k8.row.col.f32.tf32.tf32.f32 "
        "{%0,%1,%2,%3}, {%4,%5,%6,%7}, {%8,%9}, {%0,%1,%2,%3};\n"
        : "+f"(c[0]), "+f"(c[1]), "+f"(c[2]), "+f"(c[3])
        : "r"(a[0]), "r"(a[1]), "r"(a[2]), "r"(a[3]), "r"(b[0]), "r"(b[1]));
}
__device__ __forceinline__ void mma16(float* c, const uint32_t* a, const uint32_t* b) {
    asm volatile(
        "mma.sync.aligned.m16n8k16.row.col.f32.f16.f16.f32 "
        "{%0,%1,%2,%3}, {%4,%5,%6,%7}, {%8,%9}, {%0,%1,%2,%3};\n"
        : "+f"(c[0]), "+f"(c[1]), "+f"(c[2]), "+f"(c[3])
        : "r"(a[0]), "r"(a[1]), "r"(a[2]), "r"(a[3]), "r"(b[0]), "r"(b[1]));
}
__device__ __forceinline__ void ldsm4(uint32_t& r0, uint32_t& r1, uint32_t& r2,
                                      uint32_t& r3, uint32_t addr) {
    asm volatile("ldmatrix.sync.aligned.m8n8.x4.shared.b16 {%0,%1,%2,%3}, [%4];\n"
                 : "=r"(r0), "=r"(r1), "=r"(r2), "=r"(r3) : "r"(addr));
}
__device__ __forceinline__ void cpa16(uint32_t saddr, const void* g, int srcsz) {
    asm volatile("cp.async.ca.shared.global [%0], [%1], 16, %2;\n"
                 :: "r"(saddr), "l"(g), "r"(srcsz));
}
__device__ __forceinline__ void cp_commit() { asm volatile("cp.async.commit_group;\n"); }
__device__ __forceinline__ void cp_wait1()  { asm volatile("cp.async.wait_group 1;\n"); }
__device__ __forceinline__ void osm(float& m, float& s, float om, float os) {
    float M = fmaxf(m, om);
    s = s * __expf(m - M) + os * __expf(om - M);
    m = M;
}
__device__ __forceinline__ void mark_done(int* ctr) {
    __threadfence();
    __syncthreads();
    if (threadIdx.x == 0) atomicAdd(ctr, 1);
}
__device__ __forceinline__ void spin_ge(int* ctr, int target) {
    if (threadIdx.x == 0) {
        while (atomicAdd(ctr, 0) < target) __nanosleep(64);
    }
    __syncthreads();
    __threadfence();
}

// ---------------- fp16 mma building blocks ---------------------------------
template <int NB>
__device__ __forceinline__ void ldg_half(float4 (&buf)[NB], int base,
        int nA, const float* __restrict__ A, int lda,
        const float* __restrict__ W, int ldw, int wvalid, int k0, int tid) {
#pragma unroll
    for (int q = 0; q < NB; q++) {
        int idx4 = tid + (base + q) * 256;
        int row = idx4 >> 3, kp = (idx4 & 7) * 4;
        float4 v;
        if (row < nA) v = *(const float4*)(A + (size_t)row * lda + k0 + kp);
        else {
            int wr = row - nA;
            if (wr < wvalid) v = *(const float4*)(W + (size_t)wr * ldw + k0 + kp);
            else             v = make_float4(0.f, 0.f, 0.f, 0.f);
        }
        buf[q] = v;
    }
}
template <int NB>
__device__ __forceinline__ void sts_half(const float4 (&buf)[NB], int base,
                                         uint32_t s0, int tid) {
#pragma unroll
    for (int q = 0; q < NB; q++) {
        int idx4 = tid + (base + q) * 256;
        int row = idx4 >> 3, kp = (idx4 & 7) * 4;
        __half2 h0 = __floats2half2_rn(buf[q].x, buf[q].y);
        __half2 h1 = __floats2half2_rn(buf[q].z, buf[q].w);
        uint32_t u0 = *(uint32_t*)&h0, u1 = *(uint32_t*)&h1;
        asm volatile("st.shared.v2.b32 [%0], {%1, %2};\n"
                     :: "r"(s0 + (uint32_t)(row * KS2 + kp) * 2), "r"(u0), "r"(u1));
    }
}
__device__ __forceinline__ void compute_k16(uint32_t sb, const uint32_t* relA,
                                            const uint32_t* relB, int kk,
                                            float c[2][8][4]) {
    uint32_t ko = sb + (uint32_t)kk * 32;
    uint32_t a[2][4];
    ldsm4(a[0][0], a[0][1], a[0][2], a[0][3], ko + relA[0]);
    ldsm4(a[1][0], a[1][1], a[1][2], a[1][3], ko + relA[1]);
#pragma unroll
    for (int jj = 0; jj < 4; jj++) {
        uint32_t r[4];
        ldsm4(r[0], r[1], r[2], r[3], ko + relB[jj]);
        uint32_t b0[2] = {r[0], r[2]}, b1[2] = {r[1], r[3]};
#pragma unroll
        for (int i = 0; i < 2; i++) {
            mma16(c[i][jj * 2],     a[i], b0);
            mma16(c[i][jj * 2 + 1], a[i], b1);
        }
    }
}

// ---------------- tf32 warp mma (gates role) --------------------------------
__device__ __forceinline__ void warp_mma(const uint32_t* __restrict__ sA,
                                         const uint32_t* __restrict__ sW,
                                         int wm, int wn, int g, int t,
                                         float c[2][8][4]) {
#pragma unroll
    for (int kk = 0; kk < 4; kk++) {
        int kb = kk * 8;
        uint32_t a[2][4];
#pragma unroll
        for (int i = 0; i < 2; i++) {
            int r = wm + i * 16 + g;
            a[i][0] = sA[r * SPAD + kb + t];     a[i][1] = sA[(r + 8) * SPAD + kb + t];
            a[i][2] = sA[r * SPAD + kb + t + 4]; a[i][3] = sA[(r + 8) * SPAD + kb + t + 4];
        }
        uint32_t bf[8][2];
#pragma unroll
        for (int j = 0; j < 8; j++) {
            int n = wn + j * 8 + g;
            bf[j][0] = sW[n * SPAD + kb + t]; bf[j][1] = sW[n * SPAD + kb + t + 4];
        }
#pragma unroll
        for (int i = 0; i < 2; i++)
#pragma unroll
            for (int j = 0; j < 8; j++) mma8(c[i][j], a[i], bf[j]);
    }
}

// ---------------- roles ------------------------------------------------------
__device__ void role_gates(uint32_t* dyn, int bx,
        const int* __restrict__ dec, const float* __restrict__ sr,
        const float* __restrict__ emb, const float* __restrict__ prev,
        const float* __restrict__ W_ih, const float* __restrict__ b_ih,
        const float* __restrict__ W_hh, const float* __restrict__ b_hh) {
    uint32_t sbase = (uint32_t)__cvta_generic_to_shared(dyn);
    int tid = threadIdx.x, wid = tid >> 5, lane = tid & 31;
    int g = lane >> 2, t = lane & 3;
    int wm = (wid & 3) * 32, wn = (wid >> 2) * 64;
    bool isGi = bx < 6;
    int n0 = (isGi ? bx : bx - 6) * 128;
    int K  = isGi ? 640 : HH;
    int NIT = K / 32;
    const float* W = (isGi ? W_ih : W_hh) + (size_t)n0 * K;
    const float* bias = isGi ? b_ih : b_hh;
    float* C = isGi ? g_gi : g_gh;

    float c[2][8][4];
#pragma unroll
    for (int i = 0; i < 2; i++)
#pragma unroll
        for (int j = 0; j < 8; j++)
#pragma unroll
            for (int q = 0; q < 4; q++) c[i][j][q] = 0.f;

    auto loadA = [&](int stage, int k0) {
        uint32_t s0 = sbase + (uint32_t)stage * (STG_G * 4);
        if (isGi) {
            for (int idx = tid; idx < 1024; idx += 256) {
                int row = idx >> 3, kp = (idx & 7) * 4;
                const float* src;
                if (k0 < 512) src = sr + (size_t)row * 512 + k0 + kp;
                else          src = emb + (size_t)dec[row] * EE + (k0 - 512) + kp;
                cpa16(s0 + (row * SPAD + kp) * 4, src, 16);
            }
        } else {
            for (int idx = tid; idx < 1024; idx += 256) {
                int row = idx >> 3, kp = (idx & 7) * 4;
                cpa16(s0 + (row * SPAD + kp) * 4, prev + (size_t)row * HH + k0 + kp, 16);
            }
        }
        for (int idx = tid; idx < 1024; idx += 256) {
            int row = idx >> 3, kp = (idx & 7) * 4;
            cpa16(s0 + ((128 + row) * SPAD + kp) * 4, W + (size_t)row * K + k0 + kp, 16);
        }
    };

    loadA(0, 0);  cp_commit();
    loadA(1, 32); cp_commit();
    for (int it = 0; it < NIT; it++) {
        cp_wait1();
        __syncthreads();
        const uint32_t* s = dyn + (it & 1) * STG_G;
        warp_mma(s, s + 128 * SPAD, wm, wn, g, t, c);
        __syncthreads();
        if (it + 2 < NIT) loadA(it & 1, (it + 2) * 32);
        cp_commit();
    }
#pragma unroll
    for (int i = 0; i < 2; i++) {
        int r = wm + i * 16 + g;
#pragma unroll
        for (int j = 0; j < 8; j++) {
            int col = n0 + wn + j * 8 + 2 * t;
            float b0 = bias[col], b1 = bias[col + 1];
            C[(size_t)r * G3 + col]           = c[i][j][0] + b0;
            C[(size_t)r * G3 + col + 1]       = c[i][j][1] + b1;
            C[(size_t)(r + 8) * G3 + col]     = c[i][j][2] + b0;
            C[(size_t)(r + 8) * G3 + col + 1] = c[i][j][3] + b1;
        }
    }
    mark_done(&g_c_gates);
}

__device__ void role_gru(int b, const float* __restrict__ hprev,
                         float* __restrict__ out_dh) {
    spin_ge(&g_c_gates, 12);
    int j = threadIdx.x;
    const float* gi = g_gi + b * G3;
    const float* gh = g_gh + b * G3;
    float r  = 1.f / (1.f + expf(-(gi[j] + gh[j])));
    float z  = 1.f / (1.f + expf(-(gi[HH+j] + gh[HH+j])));
    float n  = tanhf(gi[2*HH+j] + r * gh[2*HH+j]);
    float h  = hprev[b * HH + j];
    float dh = (1.f - z) * n + z * h;
    g_dh[b*HH+j]   = dh;
    out_dh[b*HH+j] = dh;
    mark_done(&g_c_gru);
}

__device__ void role_merge(int b) {
    extern __shared__ uint32_t dyn[];
    float* sm_ = (float*)dyn;
    float* ss_ = sm_ + 256;
    spin_ge(&g_c_tiles, NBE + NBG);
    int tid = threadIdx.x;
    float m = -1e30f, s = 0.f;
    for (int i = tid; i < NBG; i += 256) osm(m, s, g_pmax[b * NBG + i], g_psum[b * NBG + i]);
    for (int t2 = tid; t2 < TT; t2 += 256) osm(m, s, g_scraw[b * TT + t2], 1.f);
    sm_[tid] = m; ss_[tid] = s; __syncthreads();
    for (int st = 128; st > 0; st >>= 1) {
        if (tid < st) {
            float m2 = sm_[tid], s2 = ss_[tid];
            osm(m2, s2, sm_[tid + st], ss_[tid + st]);
            sm_[tid] = m2; ss_[tid] = s2;
        }
        __syncthreads();
    }
    if (tid == 0) { g_M[b] = sm_[0]; g_invS[b] = 1.f / ss_[0]; }
    mark_done(&g_c_merge);
}

__device__ void role_out(int idx, float* __restrict__ out) {
    spin_ge(&g_c_merge, BB);
    int b = idx % BB, seg = idx / BB;     // 13 segments of 4096 cols
    int tid = threadIdx.x;
    float M = g_M[b], inv = g_invS[b];
    const __half* sg = g_scoreh + (size_t)b * VVP;
    float* orow = out + (size_t)b * VO;
#pragma unroll
    for (int l = 0; l < 4; l++) {
        int c0 = seg * 4096 + l * 1024 + tid * 4;
        if (c0 + 3 < VV) {
            __half2 q0 = *(const __half2*)(sg + c0);
            __half2 q1 = *(const __half2*)(sg + c0 + 2);
            orow[c0 + 0] = __expf(__half2float(__low2half(q0))  - M) * inv;
            orow[c0 + 1] = __expf(__half2float(__high2half(q0)) - M) * inv;
            orow[c0 + 2] = __expf(__half2float(__low2half(q1))  - M) * inv;
            orow[c0 + 3] = __expf(__half2float(__high2half(q1)) - M) * inv;
        } else {
            for (int cc = c0; cc < VV && cc < c0 + 4; cc++)
                orow[cc] = __expf(__half2float(sg[cc]) - M) * inv;
        }
    }
    mark_done(&g_c_out);
}

__device__ void role_tail(int b, const int* __restrict__ idxs,
                          const int* __restrict__ dec,
                          const float* __restrict__ EO,
                          float* __restrict__ out, float* __restrict__ out_sr) {
    extern __shared__ uint32_t dyn[];
    float* pc = (float*)dyn;          // [TT]
    int*   mt = (int*)(pc + TT);      // [TT]
    int*   cntp = (int*)(mt + TT);
    spin_ge(&g_c_out, NOUT);          // scatter must follow out's row stores
    int tid = threadIdx.x;
    float M = g_M[b], inv = g_invS[b];
    float* orow = out + (size_t)b * VO;
    if (tid == 0) *cntp = 0;
    for (int t2 = tid; t2 < TT; t2 += 256)
        pc[t2] = __expf(g_scraw[b * TT + t2] - M) * inv;
    if (tid < NOOV) orow[VV + tid] = 1e-4f;
    __syncthreads();
    int d = dec[b];
    for (int t2 = tid; t2 < TT; t2 += 256) {
        atomicAdd(&orow[idxs[b * TT + t2]], pc[t2]);
        if (idxs[b * TT + t2] == d) { int p = atomicAdd(cntp, 1); mt[p] = t2; }
    }
    __syncthreads();
    int n = *cntp;
    float scale = (n > 1) ? 1.f / (float)n : 1.f;
    for (int e = tid; e < 2 * HH; e += 256) {
        float acc = 0.f;
        for (int k = 0; k < n; k++) {
            int t2 = mt[k];
            acc += pc[t2] * scale * EO[((size_t)b * TT + t2) * (2 * HH) + e];
        }
        out_sr[b * 2 * HH + e] = acc;
    }
    // last tail block resets all counters for the next graph replay
    __threadfence();
    __syncthreads();
    if (tid == 0) {
        int v = atomicAdd(&g_c_tail, 1);
        if (v == BB - 1) {
            atomicExch(&g_c_gates, 0); atomicExch(&g_c_gru, 0);
            atomicExch(&g_c_tiles, 0); atomicExch(&g_c_merge, 0);
            atomicExch(&g_c_out, 0);   atomicExch(&g_c_tail, 0);
        }
    }
}

// ---------------- fused kernel -----------------------------------------------
__global__ void __launch_bounds__(256, 2) k_fused(
        const int* __restrict__ dec, const float* __restrict__ sr,
        const float* __restrict__ emb, const float* __restrict__ prev,
        const float* __restrict__ W_ih, const float* __restrict__ b_ih,
        const float* __restrict__ W_hh, const float* __restrict__ b_hh,
        const float* __restrict__ Wg, const float* __restrict__ gbias,
        const float* __restrict__ EO, const float* __restrict__ Wc,
        const float* __restrict__ cbias, const int* __restrict__ idxs,
        float* __restrict__ out, float* __restrict__ out_dh,
        float* __restrict__ out_sr) {
    extern __shared__ uint32_t dyn[];
    int bid = blockIdx.x;
    if (bid < OFF_GRU) { role_gates(dyn, bid, dec, sr, emb, prev, W_ih, b_ih, W_hh, b_hh); return; }
    if (bid < OFF_ENC) { role_gru(bid - OFF_GRU, prev, out_dh); return; }
    if (bid >= OFF_TAIL)  { role_tail(bid - OFF_TAIL, idxs, dec, EO, out, out_sr); return; }
    if (bid >= OFF_OUT)   { role_out(bid - OFF_OUT, out); return; }
    if (bid >= OFF_MERGE) { role_merge(bid - OFF_MERGE); return; }

    // ---- GEMM tiles (enc / gemmg), fp16 mma.sync pipeline --------------------
    uint32_t sbase = (uint32_t)__cvta_generic_to_shared(dyn);
    int tid = threadIdx.x, wid = tid >> 5, lane = tid & 31;
    int g = lane >> 2, t = lane & 3;
    bool isg = bid >= OFF_GEMG;

    int lr = lane & 7;
    int rowadj = ((lane >> 3) & 1) * 8 + lr;
    int kadj = (lane >> 4) * 8;

    float c[2][8][4];
#pragma unroll
    for (int i = 0; i < 2; i++)
#pragma unroll
        for (int j = 0; j < 8; j++)
#pragma unroll
            for (int q = 0; q < 4; q++) c[i][j][q] = 0.f;

    if (isg) {
        // ============ gemmg: 128x128, K=256, NIT=8 =========================
        int bx = bid - OFF_GEMG;
        spin_ge(&g_c_gru, BB);                       // A = g_dh must be ready
        int wm = (wid & 3) * 32, wn = (wid >> 2) * 64;
        const float* A = g_dh;   const int lda = HH;   const int nA = 128;
        const float* W = Wg + (size_t)bx * 128 * HH;   const int ldw = HH;
        int wvalid = VV - bx * 128; if (wvalid > 128) wvalid = 128;
        const int NIT = 8;
        uint32_t st0 = sbase, st1 = sbase + STGB_G;
        uint32_t relA[2], relB[4];
#pragma unroll
        for (int i = 0; i < 2; i++)
            relA[i] = (uint32_t)((wm + i * 16 + rowadj) * KS2 + kadj) * 2;
#pragma unroll
        for (int j = 0; j < 4; j++)
            relB[j] = (uint32_t)((nA + wn + j * 16 + rowadj) * KS2 + kadj) * 2;

        float4 buf[4];
        ldg_half<4>(buf, 0, nA, A, lda, W, ldw, wvalid, 0, tid);
        sts_half<4>(buf, 0, st0, tid);
        ldg_half<4>(buf, 4, nA, A, lda, W, ldw, wvalid, 0, tid);
        sts_half<4>(buf, 4, st0, tid);
        __syncthreads();
        for (int it = 0; it < NIT; it++) {
            uint32_t scur = (it & 1) ? st1 : st0;
            uint32_t snxt = (it & 1) ? st0 : st1;
            bool more = (it + 1 < NIT);
            if (more) ldg_half<4>(buf, 0, nA, A, lda, W, ldw, wvalid, (it + 1) * 32, tid);
            compute_k16(scur, relA, relB, 0, c);
            if (more) { sts_half<4>(buf, 0, snxt, tid);
                        ldg_half<4>(buf, 4, nA, A, lda, W, ldw, wvalid, (it + 1) * 32, tid); }
            compute_k16(scur, relA, relB, 1, c);
            if (more) sts_half<4>(buf, 4, snxt, tid);
            __syncthreads();
        }
        // epilogue: half store (+bias) and per-tile online (max, sumexp)
        int n0 = bx * 128;
        float lm[2][2], ls[2][2];
#pragma unroll
        for (int i = 0; i < 2; i++)
#pragma unroll
            for (int h = 0; h < 2; h++) { lm[i][h] = -1e30f; ls[i][h] = 0.f; }
#pragma unroll
        for (int i = 0; i < 2; i++) {
            int r = wm + i * 16 + g;
#pragma unroll
            for (int j = 0; j < 8; j++) {
                int col = n0 + wn + j * 8 + 2 * t;
                if (col < VV) {
                    bool p1 = (col + 1 < VV);
                    float b0 = gbias[col];
                    float b1 = p1 ? gbias[col + 1] : 0.f;
                    __half2 h02 = __floats2half2_rn(c[i][j][0] + b0, c[i][j][1] + b1);
                    __half2 h23 = __floats2half2_rn(c[i][j][2] + b0, c[i][j][3] + b1);
                    *(__half2*)(g_scoreh + (size_t)r * VVP + col)       = h02;
                    *(__half2*)(g_scoreh + (size_t)(r + 8) * VVP + col) = h23;
                    float w0 = __half2float(__low2half(h02));
                    float w1 = __half2float(__high2half(h02));
                    float w2 = __half2float(__low2half(h23));
                    float w3 = __half2float(__high2half(h23));
                    lm[i][0] = fmaxf(lm[i][0], w0);
                    lm[i][1] = fmaxf(lm[i][1], w2);
                    if (p1) { lm[i][0] = fmaxf(lm[i][0], w1); lm[i][1] = fmaxf(lm[i][1], w3); }
                }
            }
        }
#pragma unroll
        for (int i = 0; i < 2; i++)
#pragma unroll
            for (int j = 0; j < 8; j++) {
                int col = n0 + wn + j * 8 + 2 * t;
                if (col < VV) {
                    bool p1 = (col + 1 < VV);
                    float b0 = gbias[col];
                    float b1 = p1 ? gbias[col + 1] : 0.f;
                    float w0 = __half2float(__float2half_rn(c[i][j][0] + b0));
                    float w2 = __half2float(__float2half_rn(c[i][j][2] + b0));
                    ls[i][0] += __expf(w0 - lm[i][0]);
                    ls[i][1] += __expf(w2 - lm[i][1]);
                    if (p1) {
                        float w1 = __half2float(__float2half_rn(c[i][j][1] + b1));
                        float w3 = __half2float(__float2half_rn(c[i][j][3] + b1));
                        ls[i][0] += __expf(w1 - lm[i][0]);
                        ls[i][1] += __expf(w3 - lm[i][1]);
                    }
                }
            }
        __syncthreads();
        float* redm = (float*)dyn;
        float* reds = redm + 256;
#pragma unroll
        for (int i = 0; i < 2; i++)
#pragma unroll
            for (int h = 0; h < 2; h++) {
                float m = lm[i][h], s = ls[i][h];
#pragma unroll
                for (int off = 1; off <= 2; off <<= 1) {
                    float om = __shfl_xor_sync(0xffffffffu, m, off);
                    float os = __shfl_xor_sync(0xffffffffu, s, off);
                    osm(m, s, om, os);
                }
                if (t == 0) {
                    int row = wm + i * 16 + h * 8 + g;
                    redm[row * 2 + (wid >> 2)] = m;
                    reds[row * 2 + (wid >> 2)] = s;
                }
            }
        __syncthreads();
        if (tid < 128) {
            float m = redm[tid * 2], s = reds[tid * 2];
            osm(m, s, redm[tid * 2 + 1], reds[tid * 2 + 1]);
            g_pmax[tid * NBG + bx] = m;
            g_psum[tid * NBG + bx] = s;
        }
        mark_done(&g_c_tiles);
    } else {
        // ============ enc: 64x256, K=512, NIT=16 ============================
        int bx = bid - OFF_ENC;
        int wm = (wid & 1) * 32, wn = (wid >> 1) * 64;
        int r0 = bx * 64;
        const float* A = EO + (size_t)r0 * (2 * HH);  const int lda = 2 * HH;
        const int nA = 64;
        const float* W = Wc;  const int ldw = 2 * HH; const int wvalid = 256;
        const int NIT = 16;
        uint32_t st0 = sbase, st1 = sbase + STGB_E;
        uint32_t relA[2], relB[4];
#pragma unroll
        for (int i = 0; i < 2; i++)
            relA[i] = (uint32_t)((wm + i * 16 + rowadj) * KS2 + kadj) * 2;
#pragma unroll
        for (int j = 0; j < 4; j++)
            relB[j] = (uint32_t)((nA + wn + j * 16 + rowadj) * KS2 + kadj) * 2;

        float4 buf[5];
        ldg_half<5>(buf, 0, nA, A, lda, W, ldw, wvalid, 0, tid);
        sts_half<5>(buf, 0, st0, tid);
        ldg_half<5>(buf, 5, nA, A, lda, W, ldw, wvalid, 0, tid);
        sts_half<5>(buf, 5, st0, tid);
        __syncthreads();
        for (int it = 0; it < NIT; it++) {
            uint32_t scur = (it & 1) ? st1 : st0;
            uint32_t snxt = (it & 1) ? st0 : st1;
            bool more = (it + 1 < NIT);
            if (more) ldg_half<5>(buf, 0, nA, A, lda, W, ldw, wvalid, (it + 1) * 32, tid);
            compute_k16(scur, relA, relB, 0, c);
            if (more) { sts_half<5>(buf, 0, snxt, tid);
                        ldg_half<5>(buf, 5, nA, A, lda, W, ldw, wvalid, (it + 1) * 32, tid); }
            compute_k16(scur, relA, relB, 1, c);
            if (more) sts_half<5>(buf, 5, snxt, tid);
            __syncthreads();
        }
        // epilogue needs dh
        spin_ge(&g_c_gru, BB);
        float rs[2][2] = {{0.f, 0.f}, {0.f, 0.f}};
#pragma unroll
        for (int i = 0; i < 2; i++) {
            int grow = r0 + wm + i * 16 + g;
            int b0r = grow / TT;
            int b1r = (grow + 8) / TT;
#pragma unroll
            for (int j = 0; j < 8; j++) {
                int col = wn + j * 8 + 2 * t;
                float bi0 = cbias[col], bi1 = cbias[col + 1];
                rs[i][0] += tanhf(c[i][j][0] + bi0) * g_dh[b0r * HH + col]
                          + tanhf(c[i][j][1] + bi1) * g_dh[b0r * HH + col + 1];
                rs[i][1] += tanhf(c[i][j][2] + bi0) * g_dh[b1r * HH + col]
                          + tanhf(c[i][j][3] + bi1) * g_dh[b1r * HH + col + 1];
            }
        }
        __syncthreads();
        float* red = (float*)dyn;
#pragma unroll
        for (int i = 0; i < 2; i++)
#pragma unroll
            for (int h = 0; h < 2; h++) {
                float v = rs[i][h];
                v += __shfl_xor_sync(0xffffffffu, v, 1);
                v += __shfl_xor_sync(0xffffffffu, v, 2);
                if (t == 0) red[(wm + i * 16 + h * 8 + g) * 4 + (wid >> 1)] = v;
            }
        __syncthreads();
        if (tid < 64) {
            float tot = red[tid * 4] + red[tid * 4 + 1] + red[tid * 4 + 2] + red[tid * 4 + 3];
            float v = tanhf(tot);
            int grow = r0 + tid;
            if (idxs[grow] == 0) v -= 10000.f;
            g_scraw[grow] = v;
        }
        mark_done(&g_c_tiles);
    }
}

// ---------------- launch ----------------------------------------------------
extern "C" void kernel_launch(void* const* d_in, const int* in_sizes, int n_in,
                              void* d_out, int out_size) {
    const int*   dec  = (const int*)d_in[0];
    const float* EO   = (const float*)d_in[1];
    const int*   idxs = (const int*)d_in[2];
    const float* prev = (const float*)d_in[3];
    const float* sr   = (const float*)d_in[4];
    int off = (n_in >= 17 && in_sizes[5] == 1) ? 1 : 0;
    const float* emb  = (const float*)d_in[5 + off];
    const float* W_ih = (const float*)d_in[6 + off];
    const float* W_hh = (const float*)d_in[7 + off];
    const float* b_ih = (const float*)d_in[8 + off];
    const float* b_hh = (const float*)d_in[9 + off];
    const float* Wg_w = (const float*)d_in[12 + off];
    const float* Wg_b = (const float*)d_in[13 + off];
    const float* Wc_w = (const float*)d_in[14 + off];
    const float* Wc_b = (const float*)d_in[15 + off];

    float* out    = (float*)d_out;
    float* out_dh = out + (size_t)BB * VO;
    float* out_sr = out_dh + (size_t)BB * HH;

    cudaFuncSetAttribute(k_fused, cudaFuncAttributeMaxDynamicSharedMemorySize, DYN_FUSED);

    k_fused<<<NBLK, 256, DYN_FUSED>>>(dec, sr, emb, prev, W_ih, b_ih, W_hh, b_hh,
                                      Wg_w, Wg_b, EO, Wc_w, Wc_b, idxs,
                                      out, out_dh, out_sr);
}

// round 15
// speedup vs baseline: 1.1908x; 1.0128x over previous
#include <cuda_runtime.h>
#include <cuda_fp16.h>
#include <math.h>
#include <stdint.h>

#define BB   128
#define TT   200
#define VV   50257
#define VVP  50264          // half row stride, 16B-aligned rows
#define HH   256
#define EE   128
#define NOOV 50
#define G3   768
#define VO   (VV + NOOV)
#define BT   (BB * TT)
#define SPAD 36             // tf32 gates smem stride (words)

#define NBG  393            // score_g tiles 128x128
#define NBE  400            // enc tiles 64x256
#define NSEG 13             // out segments per row (13 x 4096 cols)
#define NOUT (NSEG * BB)

// fused-kernel block layout (dependencies always point to lower bids)
#define OFF_GATES 0
#define OFF_GRU   12
#define OFF_ENC   140
#define OFF_GEMG  (OFF_ENC + NBE)      // 540
#define OFF_MERGE (OFF_GEMG + NBG)     // 933
#define OFF_OUT   (OFF_MERGE + BB)     // 1061
#define OFF_TAIL  (OFF_OUT + NOUT)     // 2725
#define NBLK      (OFF_TAIL + BB)      // 2853

#define STG_G ((128 + 128) * SPAD)     // gates stage words
#define DYN_FUSED (2 * STG_G * 4)      // 73728 B

// fp16 mma smem: row stride 40 halfs (80B) -> conflict-free LDSM
#define KS2      40
#define STGB_G   (256 * KS2 * 2)       // 20480 B
#define STGB_E   (320 * KS2 * 2)       // 25600 B

// ---------------- scratch ----------------------------------------------
__device__ float  g_gi[BB * G3];
__device__ float  g_gh[BB * G3];
__device__ float  g_dh[BB * HH];
__device__ __half g_scoreh[BB * VVP];
__device__ float  g_scraw[BT];
__device__ float  g_pmax[BB * NBG];
__device__ float  g_psum[BB * NBG];
__device__ float  g_M[BB];
__device__ float  g_invS[BB];
__device__ int    g_c_gates;       // zero-init; reset by last tail block
__device__ int    g_c_gru;
__device__ int    g_c_tiles;
__device__ int    g_c_tail;
__device__ int    g_row_merge[BB]; // per-row: merge done flag
__device__ int    g_row_out[BB];   // per-row: # out segments done

// ---------------- helpers ------------------------------------------------
__device__ __forceinline__ void mma8(float* c, const uint32_t* a, const uint32_t* b) {
    asm volatile(
        "mma.sync.aligned.m16n8k8.row.col.f32.tf32.tf32.f32 "
        "{%0,%1,%2,%3}, {%4,%5,%6,%7}, {%8,%9}, {%0,%1,%2,%3};\n"
        : "+f"(c[0]), "+f"(c[1]), "+f"(c[2]), "+f"(c[3])
        : "r"(a[0]), "r"(a[1]), "r"(a[2]), "r"(a[3]), "r"(b[0]), "r"(b[1]));
}
__device__ __forceinline__ void mma16(float* c, const uint32_t* a, const uint32_t* b) {
    asm volatile(
        "mma.sync.aligned.m16n8k16.row.col.f32.f16.f16.f32 "
        "{%0,%1,%2,%3}, {%4,%5,%6,%7}, {%8,%9}, {%0,%1,%2,%3};\n"
        : "+f"(c[0]), "+f"(c[1]), "+f"(c[2]), "+f"(c[3])
        : "r"(a[0]), "r"(a[1]), "r"(a[2]), "r"(a[3]), "r"(b[0]), "r"(b[1]));
}
__device__ __forceinline__ void ldsm4(uint32_t& r0, uint32_t& r1, uint32_t& r2,
                                      uint32_t& r3, uint32_t addr) {
    asm volatile("ldmatrix.sync.aligned.m8n8.x4.shared.b16 {%0,%1,%2,%3}, [%4];\n"
                 : "=r"(r0), "=r"(r1), "=r"(r2), "=r"(r3) : "r"(addr));
}
__device__ __forceinline__ void cpa16(uint32_t saddr, const void* g, int srcsz) {
    asm volatile("cp.async.ca.shared.global [%0], [%1], 16, %2;\n"
                 :: "r"(saddr), "l"(g), "r"(srcsz));
}
__device__ __forceinline__ void cp_commit() { asm volatile("cp.async.commit_group;\n"); }
__device__ __forceinline__ void cp_wait1()  { asm volatile("cp.async.wait_group 1;\n"); }
__device__ __forceinline__ void osm(float& m, float& s, float om, float os) {
    float M = fmaxf(m, om);
    s = s * __expf(m - M) + os * __expf(om - M);
    m = M;
}
__device__ __forceinline__ void mark_done(int* ctr) {
    __threadfence();
    __syncthreads();
    if (threadIdx.x == 0) atomicAdd(ctr, 1);
}
__device__ __forceinline__ void spin_ge(int* ctr, int target) {
    if (threadIdx.x == 0) {
        while (atomicAdd(ctr, 0) < target) __nanosleep(64);
    }
    __syncthreads();
    __threadfence();
}

// ---------------- fp16 mma building blocks ---------------------------------
template <int NB>
__device__ __forceinline__ void ldg_half(float4 (&buf)[NB], int base,
        int nA, const float* __restrict__ A, int lda,
        const float* __restrict__ W, int ldw, int wvalid, int k0, int tid) {
#pragma unroll
    for (int q = 0; q < NB; q++) {
        int idx4 = tid + (base + q) * 256;
        int row = idx4 >> 3, kp = (idx4 & 7) * 4;
        float4 v;
        if (row < nA) v = *(const float4*)(A + (size_t)row * lda + k0 + kp);
        else {
            int wr = row - nA;
            if (wr < wvalid) v = *(const float4*)(W + (size_t)wr * ldw + k0 + kp);
            else             v = make_float4(0.f, 0.f, 0.f, 0.f);
        }
        buf[q] = v;
    }
}
template <int NB>
__device__ __forceinline__ void sts_half(const float4 (&buf)[NB], int base,
                                         uint32_t s0, int tid) {
#pragma unroll
    for (int q = 0; q < NB; q++) {
        int idx4 = tid + (base + q) * 256;
        int row = idx4 >> 3, kp = (idx4 & 7) * 4;
        __half2 h0 = __floats2half2_rn(buf[q].x, buf[q].y);
        __half2 h1 = __floats2half2_rn(buf[q].z, buf[q].w);
        uint32_t u0 = *(uint32_t*)&h0, u1 = *(uint32_t*)&h1;
        asm volatile("st.shared.v2.b32 [%0], {%1, %2};\n"
                     :: "r"(s0 + (uint32_t)(row * KS2 + kp) * 2), "r"(u0), "r"(u1));
    }
}
__device__ __forceinline__ void compute_k16(uint32_t sb, const uint32_t* relA,
                                            const uint32_t* relB, int kk,
                                            float c[2][8][4]) {
    uint32_t ko = sb + (uint32_t)kk * 32;
    uint32_t a[2][4];
    ldsm4(a[0][0], a[0][1], a[0][2], a[0][3], ko + relA[0]);
    ldsm4(a[1][0], a[1][1], a[1][2], a[1][3], ko + relA[1]);
#pragma unroll
    for (int jj = 0; jj < 4; jj++) {
        uint32_t r[4];
        ldsm4(r[0], r[1], r[2], r[3], ko + relB[jj]);
        uint32_t b0[2] = {r[0], r[2]}, b1[2] = {r[1], r[3]};
#pragma unroll
        for (int i = 0; i < 2; i++) {
            mma16(c[i][jj * 2],     a[i], b0);
            mma16(c[i][jj * 2 + 1], a[i], b1);
        }
    }
}

// ---------------- tf32 warp mma (gates role) --------------------------------
__device__ __forceinline__ void warp_mma(const uint32_t* __restrict__ sA,
                                         const uint32_t* __restrict__ sW,
                                         int wm, int wn, int g, int t,
                                         float c[2][8][4]) {
#pragma unroll
    for (int kk = 0; kk < 4; kk++) {
        int kb = kk * 8;
        uint32_t a[2][4];
#pragma unroll
        for (int i = 0; i < 2; i++) {
            int r = wm + i * 16 + g;
            a[i][0] = sA[r * SPAD + kb + t];     a[i][1] = sA[(r + 8) * SPAD + kb + t];
            a[i][2] = sA[r * SPAD + kb + t + 4]; a[i][3] = sA[(r + 8) * SPAD + kb + t + 4];
        }
        uint32_t bf[8][2];
#pragma unroll
        for (int j = 0; j < 8; j++) {
            int n = wn + j * 8 + g;
            bf[j][0] = sW[n * SPAD + kb + t]; bf[j][1] = sW[n * SPAD + kb + t + 4];
        }
#pragma unroll
        for (int i = 0; i < 2; i++)
#pragma unroll
            for (int j = 0; j < 8; j++) mma8(c[i][j], a[i], bf[j]);
    }
}

// ---------------- roles ------------------------------------------------------
__device__ void role_gates(uint32_t* dyn, int bx,
        const int* __restrict__ dec, const float* __restrict__ sr,
        const float* __restrict__ emb, const float* __restrict__ prev,
        const float* __restrict__ W_ih, const float* __restrict__ b_ih,
        const float* __restrict__ W_hh, const float* __restrict__ b_hh) {
    uint32_t sbase = (uint32_t)__cvta_generic_to_shared(dyn);
    int tid = threadIdx.x, wid = tid >> 5, lane = tid & 31;
    int g = lane >> 2, t = lane & 3;
    int wm = (wid & 3) * 32, wn = (wid >> 2) * 64;
    bool isGi = bx < 6;
    int n0 = (isGi ? bx : bx - 6) * 128;
    int K  = isGi ? 640 : HH;
    int NIT = K / 32;
    const float* W = (isGi ? W_ih : W_hh) + (size_t)n0 * K;
    const float* bias = isGi ? b_ih : b_hh;
    float* C = isGi ? g_gi : g_gh;

    float c[2][8][4];
#pragma unroll
    for (int i = 0; i < 2; i++)
#pragma unroll
        for (int j = 0; j < 8; j++)
#pragma unroll
            for (int q = 0; q < 4; q++) c[i][j][q] = 0.f;

    auto loadA = [&](int stage, int k0) {
        uint32_t s0 = sbase + (uint32_t)stage * (STG_G * 4);
        if (isGi) {
            for (int idx = tid; idx < 1024; idx += 256) {
                int row = idx >> 3, kp = (idx & 7) * 4;
                const float* src;
                if (k0 < 512) src = sr + (size_t)row * 512 + k0 + kp;
                else          src = emb + (size_t)dec[row] * EE + (k0 - 512) + kp;
                cpa16(s0 + (row * SPAD + kp) * 4, src, 16);
            }
        } else {
            for (int idx = tid; idx < 1024; idx += 256) {
                int row = idx >> 3, kp = (idx & 7) * 4;
                cpa16(s0 + (row * SPAD + kp) * 4, prev + (size_t)row * HH + k0 + kp, 16);
            }
        }
        for (int idx = tid; idx < 1024; idx += 256) {
            int row = idx >> 3, kp = (idx & 7) * 4;
            cpa16(s0 + ((128 + row) * SPAD + kp) * 4, W + (size_t)row * K + k0 + kp, 16);
        }
    };

    loadA(0, 0);  cp_commit();
    loadA(1, 32); cp_commit();
    for (int it = 0; it < NIT; it++) {
        cp_wait1();
        __syncthreads();
        const uint32_t* s = dyn + (it & 1) * STG_G;
        warp_mma(s, s + 128 * SPAD, wm, wn, g, t, c);
        __syncthreads();
        if (it + 2 < NIT) loadA(it & 1, (it + 2) * 32);
        cp_commit();
    }
#pragma unroll
    for (int i = 0; i < 2; i++) {
        int r = wm + i * 16 + g;
#pragma unroll
        for (int j = 0; j < 8; j++) {
            int col = n0 + wn + j * 8 + 2 * t;
            float b0 = bias[col], b1 = bias[col + 1];
            C[(size_t)r * G3 + col]           = c[i][j][0] + b0;
            C[(size_t)r * G3 + col + 1]       = c[i][j][1] + b1;
            C[(size_t)(r + 8) * G3 + col]     = c[i][j][2] + b0;
            C[(size_t)(r + 8) * G3 + col + 1] = c[i][j][3] + b1;
        }
    }
    mark_done(&g_c_gates);
}

__device__ void role_gru(int b, const float* __restrict__ hprev,
                         float* __restrict__ out_dh) {
    spin_ge(&g_c_gates, 12);
    int j = threadIdx.x;
    const float* gi = g_gi + b * G3;
    const float* gh = g_gh + b * G3;
    float r  = 1.f / (1.f + expf(-(gi[j] + gh[j])));
    float z  = 1.f / (1.f + expf(-(gi[HH+j] + gh[HH+j])));
    float n  = tanhf(gi[2*HH+j] + r * gh[2*HH+j]);
    float h  = hprev[b * HH + j];
    float dh = (1.f - z) * n + z * h;
    g_dh[b*HH+j]   = dh;
    out_dh[b*HH+j] = dh;
    mark_done(&g_c_gru);
}

__device__ void role_merge(int b) {
    extern __shared__ uint32_t dyn[];
    float* sm_ = (float*)dyn;
    float* ss_ = sm_ + 256;
    spin_ge(&g_c_tiles, NBE + NBG);
    int tid = threadIdx.x;
    float m = -1e30f, s = 0.f;
    for (int i = tid; i < NBG; i += 256) osm(m, s, g_pmax[b * NBG + i], g_psum[b * NBG + i]);
    for (int t2 = tid; t2 < TT; t2 += 256) osm(m, s, g_scraw[b * TT + t2], 1.f);
    sm_[tid] = m; ss_[tid] = s; __syncthreads();
    for (int st = 128; st > 0; st >>= 1) {
        if (tid < st) {
            float m2 = sm_[tid], s2 = ss_[tid];
            osm(m2, s2, sm_[tid + st], ss_[tid + st]);
            sm_[tid] = m2; ss_[tid] = s2;
        }
        __syncthreads();
    }
    if (tid == 0) { g_M[b] = sm_[0]; g_invS[b] = 1.f / ss_[0]; }
    __threadfence();
    __syncthreads();
    if (tid == 0) atomicExch(&g_row_merge[b], 1);   // per-row release
}

__device__ void role_out(int idx, float* __restrict__ out) {
    int b = idx % BB, seg = idx / BB;     // 13 segments of 4096 cols
    spin_ge(&g_row_merge[b], 1);          // wait only THIS row's merge
    int tid = threadIdx.x;
    float M = g_M[b], inv = g_invS[b];
    const __half* sg = g_scoreh + (size_t)b * VVP;
    float* orow = out + (size_t)b * VO;
#pragma unroll
    for (int l = 0; l < 4; l++) {
        int c0 = seg * 4096 + l * 1024 + tid * 4;
        if (c0 + 3 < VV) {
            __half2 q0 = *(const __half2*)(sg + c0);
            __half2 q1 = *(const __half2*)(sg + c0 + 2);
            orow[c0 + 0] = __expf(__half2float(__low2half(q0))  - M) * inv;
            orow[c0 + 1] = __expf(__half2float(__high2half(q0)) - M) * inv;
            orow[c0 + 2] = __expf(__half2float(__low2half(q1))  - M) * inv;
            orow[c0 + 3] = __expf(__half2float(__high2half(q1)) - M) * inv;
        } else {
            for (int cc = c0; cc < VV && cc < c0 + 4; cc++)
                orow[cc] = __expf(__half2float(sg[cc]) - M) * inv;
        }
    }
    mark_done(&g_row_out[b]);
}

__device__ void role_tail(int b, const int* __restrict__ idxs,
                          const int* __restrict__ dec,
                          const float* __restrict__ EO,
                          float* __restrict__ out, float* __restrict__ out_sr) {
    extern __shared__ uint32_t dyn[];
    float* pc = (float*)dyn;          // [TT]
    int*   mt = (int*)(pc + TT);      // [TT]
    int*   cntp = (int*)(mt + TT);
    spin_ge(&g_row_out[b], NSEG);     // only THIS row's out segments
    int tid = threadIdx.x;
    float M = g_M[b], inv = g_invS[b];
    float* orow = out + (size_t)b * VO;
    if (tid == 0) *cntp = 0;
    for (int t2 = tid; t2 < TT; t2 += 256)
        pc[t2] = __expf(g_scraw[b * TT + t2] - M) * inv;
    if (tid < NOOV) orow[VV + tid] = 1e-4f;
    __syncthreads();
    int d = dec[b];
    for (int t2 = tid; t2 < TT; t2 += 256) {
        atomicAdd(&orow[idxs[b * TT + t2]], pc[t2]);
        if (idxs[b * TT + t2] == d) { int p = atomicAdd(cntp, 1); mt[p] = t2; }
    }
    __syncthreads();
    int n = *cntp;
    float scale = (n > 1) ? 1.f / (float)n : 1.f;
    for (int e = tid; e < 2 * HH; e += 256) {
        float acc = 0.f;
        for (int k = 0; k < n; k++) {
            int t2 = mt[k];
            acc += pc[t2] * scale * EO[((size_t)b * TT + t2) * (2 * HH) + e];
        }
        out_sr[b * 2 * HH + e] = acc;
    }
    // last tail block resets all counters for the next graph replay
    __threadfence();
    __syncthreads();
    if (tid == 0) {
        int v = atomicAdd(&g_c_tail, 1);
        if (v == BB - 1) {
            atomicExch(&g_c_gates, 0); atomicExch(&g_c_gru, 0);
            atomicExch(&g_c_tiles, 0); atomicExch(&g_c_tail, 0);
            for (int i = 0; i < BB; i++) {
                atomicExch(&g_row_merge[i], 0);
                atomicExch(&g_row_out[i], 0);
            }
        }
    }
}

// ---------------- fused kernel -----------------------------------------------
__global__ void __launch_bounds__(256, 2) k_fused(
        const int* __restrict__ dec, const float* __restrict__ sr,
        const float* __restrict__ emb, const float* __restrict__ prev,
        const float* __restrict__ W_ih, const float* __restrict__ b_ih,
        const float* __restrict__ W_hh, const float* __restrict__ b_hh,
        const float* __restrict__ Wg, const float* __restrict__ gbias,
        const float* __restrict__ EO, const float* __restrict__ Wc,
        const float* __restrict__ cbias, const int* __restrict__ idxs,
        float* __restrict__ out, float* __restrict__ out_dh,
        float* __restrict__ out_sr) {
    extern __shared__ uint32_t dyn[];
    int bid = blockIdx.x;
    if (bid < OFF_GRU) { role_gates(dyn, bid, dec, sr, emb, prev, W_ih, b_ih, W_hh, b_hh); return; }
    if (bid < OFF_ENC) { role_gru(bid - OFF_GRU, prev, out_dh); return; }
    if (bid >= OFF_TAIL)  { role_tail(bid - OFF_TAIL, idxs, dec, EO, out, out_sr); return; }
    if (bid >= OFF_OUT)   { role_out(bid - OFF_OUT, out); return; }
    if (bid >= OFF_MERGE) { role_merge(bid - OFF_MERGE); return; }

    // ---- GEMM tiles (enc / gemmg), fp16 mma.sync pipeline --------------------
    uint32_t sbase = (uint32_t)__cvta_generic_to_shared(dyn);
    int tid = threadIdx.x, wid = tid >> 5, lane = tid & 31;
    int g = lane >> 2, t = lane & 3;
    bool isg = bid >= OFF_GEMG;

    int lr = lane & 7;
    int rowadj = ((lane >> 3) & 1) * 8 + lr;
    int kadj = (lane >> 4) * 8;

    float c[2][8][4];
#pragma unroll
    for (int i = 0; i < 2; i++)
#pragma unroll
        for (int j = 0; j < 8; j++)
#pragma unroll
            for (int q = 0; q < 4; q++) c[i][j][q] = 0.f;

    if (isg) {
        // ============ gemmg: 128x128, K=256, NIT=8 =========================
        int bx = bid - OFF_GEMG;
        spin_ge(&g_c_gru, BB);
        int wm = (wid & 3) * 32, wn = (wid >> 2) * 64;
        const float* A = g_dh;   const int lda = HH;   const int nA = 128;
        const float* W = Wg + (size_t)bx * 128 * HH;   const int ldw = HH;
        int wvalid = VV - bx * 128; if (wvalid > 128) wvalid = 128;
        const int NIT = 8;
        uint32_t st0 = sbase, st1 = sbase + STGB_G;
        uint32_t relA[2], relB[4];
#pragma unroll
        for (int i = 0; i < 2; i++)
            relA[i] = (uint32_t)((wm + i * 16 + rowadj) * KS2 + kadj) * 2;
#pragma unroll
        for (int j = 0; j < 4; j++)
            relB[j] = (uint32_t)((nA + wn + j * 16 + rowadj) * KS2 + kadj) * 2;

        float4 buf[4];
        ldg_half<4>(buf, 0, nA, A, lda, W, ldw, wvalid, 0, tid);
        sts_half<4>(buf, 0, st0, tid);
        ldg_half<4>(buf, 4, nA, A, lda, W, ldw, wvalid, 0, tid);
        sts_half<4>(buf, 4, st0, tid);
        __syncthreads();
        for (int it = 0; it < NIT; it++) {
            uint32_t scur = (it & 1) ? st1 : st0;
            uint32_t snxt = (it & 1) ? st0 : st1;
            bool more = (it + 1 < NIT);
            if (more) ldg_half<4>(buf, 0, nA, A, lda, W, ldw, wvalid, (it + 1) * 32, tid);
            compute_k16(scur, relA, relB, 0, c);
            if (more) { sts_half<4>(buf, 0, snxt, tid);
                        ldg_half<4>(buf, 4, nA, A, lda, W, ldw, wvalid, (it + 1) * 32, tid); }
            compute_k16(scur, relA, relB, 1, c);
            if (more) sts_half<4>(buf, 4, snxt, tid);
            __syncthreads();
        }
        int n0 = bx * 128;
        float lm[2][2], ls[2][2];
#pragma unroll
        for (int i = 0; i < 2; i++)
#pragma unroll
            for (int h = 0; h < 2; h++) { lm[i][h] = -1e30f; ls[i][h] = 0.f; }
#pragma unroll
        for (int i = 0; i < 2; i++) {
            int r = wm + i * 16 + g;
#pragma unroll
            for (int j = 0; j < 8; j++) {
                int col = n0 + wn + j * 8 + 2 * t;
                if (col < VV) {
                    bool p1 = (col + 1 < VV);
                    float b0 = gbias[col];
                    float b1 = p1 ? gbias[col + 1] : 0.f;
                    __half2 h02 = __floats2half2_rn(c[i][j][0] + b0, c[i][j][1] + b1);
                    __half2 h23 = __floats2half2_rn(c[i][j][2] + b0, c[i][j][3] + b1);
                    *(__half2*)(g_scoreh + (size_t)r * VVP + col)       = h02;
                    *(__half2*)(g_scoreh + (size_t)(r + 8) * VVP + col) = h23;
                    float w0 = __half2float(__low2half(h02));
                    float w1 = __half2float(__high2half(h02));
                    float w2 = __half2float(__low2half(h23));
                    float w3 = __half2float(__high2half(h23));
                    lm[i][0] = fmaxf(lm[i][0], w0);
                    lm[i][1] = fmaxf(lm[i][1], w2);
                    if (p1) { lm[i][0] = fmaxf(lm[i][0], w1); lm[i][1] = fmaxf(lm[i][1], w3); }
                }
            }
        }
#pragma unroll
        for (int i = 0; i < 2; i++)
#pragma unroll
            for (int j = 0; j < 8; j++) {
                int col = n0 + wn + j * 8 + 2 * t;
                if (col < VV) {
                    bool p1 = (col + 1 < VV);
                    float b0 = gbias[col];
                    float b1 = p1 ? gbias[col + 1] : 0.f;
                    float w0 = __half2float(__float2half_rn(c[i][j][0] + b0));
                    float w2 = __half2float(__float2half_rn(c[i][j][2] + b0));
                    ls[i][0] += __expf(w0 - lm[i][0]);
                    ls[i][1] += __expf(w2 - lm[i][1]);
                    if (p1) {
                        float w1 = __half2float(__float2half_rn(c[i][j][1] + b1));
                        float w3 = __half2float(__float2half_rn(c[i][j][3] + b1));
                        ls[i][0] += __expf(w1 - lm[i][0]);
                        ls[i][1] += __expf(w3 - lm[i][1]);
                    }
                }
            }
        __syncthreads();
        float* redm = (float*)dyn;
        float* reds = redm + 256;
#pragma unroll
        for (int i = 0; i < 2; i++)
#pragma unroll
            for (int h = 0; h < 2; h++) {
                float m = lm[i][h], s = ls[i][h];
#pragma unroll
                for (int off = 1; off <= 2; off <<= 1) {
                    float om = __shfl_xor_sync(0xffffffffu, m, off);
                    float os = __shfl_xor_sync(0xffffffffu, s, off);
                    osm(m, s, om, os);
                }
                if (t == 0) {
                    int row = wm + i * 16 + h * 8 + g;
                    redm[row * 2 + (wid >> 2)] = m;
                    reds[row * 2 + (wid >> 2)] = s;
                }
            }
        __syncthreads();
        if (tid < 128) {
            float m = redm[tid * 2], s = reds[tid * 2];
            osm(m, s, redm[tid * 2 + 1], reds[tid * 2 + 1]);
            g_pmax[tid * NBG + bx] = m;
            g_psum[tid * NBG + bx] = s;
        }
        mark_done(&g_c_tiles);
    } else {
        // ============ enc: 64x256, K=512, NIT=16 ============================
        int bx = bid - OFF_ENC;
        int wm = (wid & 1) * 32, wn = (wid >> 1) * 64;
        int r0 = bx * 64;
        const float* A = EO + (size_t)r0 * (2 * HH);  const int lda = 2 * HH;
        const int nA = 64;
        const float* W = Wc;  const int ldw = 2 * HH; const int wvalid = 256;
        const int NIT = 16;
        uint32_t st0 = sbase, st1 = sbase + STGB_E;
        uint32_t relA[2], relB[4];
#pragma unroll
        for (int i = 0; i < 2; i++)
            relA[i] = (uint32_t)((wm + i * 16 + rowadj) * KS2 + kadj) * 2;
#pragma unroll
        for (int j = 0; j < 4; j++)
            relB[j] = (uint32_t)((nA + wn + j * 16 + rowadj) * KS2 + kadj) * 2;

        float4 buf[5];
        ldg_half<5>(buf, 0, nA, A, lda, W, ldw, wvalid, 0, tid);
        sts_half<5>(buf, 0, st0, tid);
        ldg_half<5>(buf, 5, nA, A, lda, W, ldw, wvalid, 0, tid);
        sts_half<5>(buf, 5, st0, tid);
        __syncthreads();
        for (int it = 0; it < NIT; it++) {
            uint32_t scur = (it & 1) ? st1 : st0;
            uint32_t snxt = (it & 1) ? st0 : st1;
            bool more = (it + 1 < NIT);
            if (more) ldg_half<5>(buf, 0, nA, A, lda, W, ldw, wvalid, (it + 1) * 32, tid);
            compute_k16(scur, relA, relB, 0, c);
            if (more) { sts_half<5>(buf, 0, snxt, tid);
                        ldg_half<5>(buf, 5, nA, A, lda, W, ldw, wvalid, (it + 1) * 32, tid); }
            compute_k16(scur, relA, relB, 1, c);
            if (more) sts_half<5>(buf, 5, snxt, tid);
            __syncthreads();
        }
        spin_ge(&g_c_gru, BB);
        float rs[2][2] = {{0.f, 0.f}, {0.f, 0.f}};
#pragma unroll
        for (int i = 0; i < 2; i++) {
            int grow = r0 + wm + i * 16 + g;
            int b0r = grow / TT;
            int b1r = (grow + 8) / TT;
#pragma unroll
            for (int j = 0; j < 8; j++) {
                int col = wn + j * 8 + 2 * t;
                float bi0 = cbias[col], bi1 = cbias[col + 1];
                rs[i][0] += tanhf(c[i][j][0] + bi0) * g_dh[b0r * HH + col]
                          + tanhf(c[i][j][1] + bi1) * g_dh[b0r * HH + col + 1];
                rs[i][1] += tanhf(c[i][j][2] + bi0) * g_dh[b1r * HH + col]
                          + tanhf(c[i][j][3] + bi1) * g_dh[b1r * HH + col + 1];
            }
        }
        __syncthreads();
        float* red = (float*)dyn;
#pragma unroll
        for (int i = 0; i < 2; i++)
#pragma unroll
            for (int h = 0; h < 2; h++) {
                float v = rs[i][h];
                v += __shfl_xor_sync(0xffffffffu, v, 1);
                v += __shfl_xor_sync(0xffffffffu, v, 2);
                if (t == 0) red[(wm + i * 16 + h * 8 + g) * 4 + (wid >> 1)] = v;
            }
        __syncthreads();
        if (tid < 64) {
            float tot = red[tid * 4] + red[tid * 4 + 1] + red[tid * 4 + 2] + red[tid * 4 + 3];
            float v = tanhf(tot);
            int grow = r0 + tid;
            if (idxs[grow] == 0) v -= 10000.f;
            g_scraw[grow] = v;
        }
        mark_done(&g_c_tiles);
    }
}

// ---------------- launch ----------------------------------------------------
extern "C" void kernel_launch(void* const* d_in, const int* in_sizes, int n_in,
                              void* d_out, int out_size) {
    const int*   dec  = (const int*)d_in[0];
    const float* EO   = (const float*)d_in[1];
    const int*   idxs = (const int*)d_in[2];
    const float* prev = (const float*)d_in[3];
    const float* sr   = (const float*)d_in[4];
    int off = (n_in >= 17 && in_sizes[5] == 1) ? 1 : 0;
    const float* emb  = (const float*)d_in[5 + off];
    const float* W_ih = (const float*)d_in[6 + off];
    const float* W_hh = (const float*)d_in[7 + off];
    const float* b_ih = (const float*)d_in[8 + off];
    const float* b_hh = (const float*)d_in[9 + off];
    const float* Wg_w = (const float*)d_in[12 + off];
    const float* Wg_b = (const float*)d_in[13 + off];
    const float* Wc_w = (const float*)d_in[14 + off];
    const float* Wc_b = (const float*)d_in[15 + off];

    float* out    = (float*)d_out;
    float* out_dh = out + (size_t)BB * VO;
    float* out_sr = out_dh + (size_t)BB * HH;

    cudaFuncSetAttribute(k_fused, cudaFuncAttributeMaxDynamicSharedMemorySize, DYN_FUSED);

    k_fused<<<NBLK, 256, DYN_FUSED>>>(dec, sr, emb, prev, W_ih, b_ih, W_hh, b_hh,
                                      Wg_w, Wg_b, EO, Wc_w, Wc_b, idxs,
                                      out, out_dh, out_sr);
}

// round 16
// speedup vs baseline: 1.1950x; 1.0035x over previous
#include <cuda_runtime.h>
#include <cuda_fp16.h>
#include <math.h>
#include <stdint.h>

#define BB   128
#define TT   200
#define VV   50257
#define VVP  50264
#define HH   256
#define EE   128
#define NOOV 50
#define G3   768
#define VO   (VV + NOOV)
#define BT   (BB * TT)

#define NBG   786           // score_g tiles 128x64
#define NBE   800           // enc tiles 64x128 (400 row-blocks x 2 col-tiles)
#define NGATE 24            // 12 gi + 12 gh tiles (128x64)
#define NSEG  13
#define NOUT  (NSEG * BB)

// block layout (dependencies point to lower bids)
#define OFF_GATES 0
#define OFF_GRU   NGATE                    // 24
#define OFF_ENC   (OFF_GRU + BB)           // 152
#define OFF_GEMG  (OFF_ENC + NBE)          // 952
#define OFF_MERGE (OFF_GEMG + NBG)         // 1738
#define OFF_OUT   (OFF_MERGE + BB)         // 1866
#define OFF_TAIL  (OFF_OUT + NOUT)         // 3530
#define NBLK      (OFF_TAIL + BB)          // 3658

// fp16 smem: row stride 40 halfs (80B), stage = 192 rows
#define KS2   40
#define STGB  (192 * KS2 * 2)              // 15360 B
#define DYN_FUSED (2 * STGB)               // 30720 B

// ---------------- scratch ----------------------------------------------
__device__ float  g_gi[BB * G3];
__device__ float  g_gh[BB * G3];
__device__ float  g_dh[BB * HH];
__device__ __half g_scoreh[BB * VVP];
__device__ float  g_scenc[BT];       // raw enc row-sums (zeroed by tail)
__device__ float  g_scraw[BT];       // masked tanh'd score_c (merge writes)
__device__ float  g_pmax[BB * NBG];
__device__ float  g_psum[BB * NBG];
__device__ float  g_M[BB];
__device__ float  g_invS[BB];
__device__ int    g_c_gates;
__device__ int    g_c_gru;
__device__ int    g_c_tiles;
__device__ int    g_c_tail;
__device__ int    g_row_merge[BB];
__device__ int    g_row_out[BB];

// ---------------- helpers ------------------------------------------------
__device__ __forceinline__ void mma16(float* c, const uint32_t* a, const uint32_t* b) {
    asm volatile(
        "mma.sync.aligned.m16n8k16.row.col.f32.f16.f16.f32 "
        "{%0,%1,%2,%3}, {%4,%5,%6,%7}, {%8,%9}, {%0,%1,%2,%3};\n"
        : "+f"(c[0]), "+f"(c[1]), "+f"(c[2]), "+f"(c[3])
        : "r"(a[0]), "r"(a[1]), "r"(a[2]), "r"(a[3]), "r"(b[0]), "r"(b[1]));
}
__device__ __forceinline__ void ldsm4(uint32_t& r0, uint32_t& r1, uint32_t& r2,
                                      uint32_t& r3, uint32_t addr) {
    asm volatile("ldmatrix.sync.aligned.m8n8.x4.shared.b16 {%0,%1,%2,%3}, [%4];\n"
                 : "=r"(r0), "=r"(r1), "=r"(r2), "=r"(r3) : "r"(addr));
}
__device__ __forceinline__ void osm(float& m, float& s, float om, float os) {
    float M = fmaxf(m, om);
    s = s * __expf(m - M) + os * __expf(om - M);
    m = M;
}
__device__ __forceinline__ void mark_done(int* ctr) {
    __threadfence();
    __syncthreads();
    if (threadIdx.x == 0) atomicAdd(ctr, 1);
}
__device__ __forceinline__ void spin_ge(int* ctr, int target) {
    if (threadIdx.x == 0) {
        while (atomicAdd(ctr, 0) < target) __nanosleep(64);
    }
    __syncthreads();
    __threadfence();
}

// store 3 float4 (converted to fp16) into stage smem
__device__ __forceinline__ void sts3(const float4 (&buf)[3], int base,
                                     uint32_t s0, int tid) {
#pragma unroll
    for (int q = 0; q < 3; q++) {
        int idx = tid + (base + q) * 256;
        int row = idx >> 3, kp = (idx & 7) * 4;
        __half2 h0 = __floats2half2_rn(buf[q].x, buf[q].y);
        __half2 h1 = __floats2half2_rn(buf[q].z, buf[q].w);
        uint32_t u0 = *(uint32_t*)&h0, u1 = *(uint32_t*)&h1;
        asm volatile("st.shared.v2.b32 [%0], {%1, %2};\n"
                     :: "r"(s0 + (uint32_t)(row * KS2 + kp) * 2), "r"(u0), "r"(u1));
    }
}
// one k16 step of a 32x32 warp tile; relB has 2 entries (2 x 16-col frags)
__device__ __forceinline__ void compute_k16(uint32_t sb, const uint32_t* relA,
                                            const uint32_t* relB, int kk,
                                            float c[2][4][4]) {
    uint32_t ko = sb + (uint32_t)kk * 32;
    uint32_t a[2][4];
    ldsm4(a[0][0], a[0][1], a[0][2], a[0][3], ko + relA[0]);
    ldsm4(a[1][0], a[1][1], a[1][2], a[1][3], ko + relA[1]);
#pragma unroll
    for (int jj = 0; jj < 2; jj++) {
        uint32_t r[4];
        ldsm4(r[0], r[1], r[2], r[3], ko + relB[jj]);
        uint32_t b0[2] = {r[0], r[2]}, b1[2] = {r[1], r[3]};
#pragma unroll
        for (int i = 0; i < 2; i++) {
            mma16(c[i][jj * 2],     a[i], b0);
            mma16(c[i][jj * 2 + 1], a[i], b1);
        }
    }
}

// ---------------- roles ------------------------------------------------------
__device__ void role_gru(int b, const float* __restrict__ hprev,
                         float* __restrict__ out_dh) {
    spin_ge(&g_c_gates, NGATE);
    int j = threadIdx.x;
    const float* gi = g_gi + b * G3;
    const float* gh = g_gh + b * G3;
    float r  = 1.f / (1.f + expf(-(gi[j] + gh[j])));
    float z  = 1.f / (1.f + expf(-(gi[HH+j] + gh[HH+j])));
    float n  = tanhf(gi[2*HH+j] + r * gh[2*HH+j]);
    float h  = hprev[b * HH + j];
    float dh = (1.f - z) * n + z * h;
    g_dh[b*HH+j]   = dh;
    out_dh[b*HH+j] = dh;
    mark_done(&g_c_gru);
}

__device__ void role_merge(int b, const int* __restrict__ idxs) {
    extern __shared__ uint32_t dyn[];
    float* sm_ = (float*)dyn;
    float* ss_ = sm_ + 256;
    spin_ge(&g_c_tiles, NBE + NBG);
    int tid = threadIdx.x;
    float m = -1e30f, s = 0.f;
    for (int i = tid; i < NBG; i += 256) osm(m, s, g_pmax[b * NBG + i], g_psum[b * NBG + i]);
    for (int t2 = tid; t2 < TT; t2 += 256) {
        float v = tanhf(g_scenc[b * TT + t2]);
        if (idxs[b * TT + t2] == 0) v -= 10000.f;
        g_scraw[b * TT + t2] = v;
        osm(m, s, v, 1.f);
    }
    sm_[tid] = m; ss_[tid] = s; __syncthreads();
    for (int st = 128; st > 0; st >>= 1) {
        if (tid < st) {
            float m2 = sm_[tid], s2 = ss_[tid];
            osm(m2, s2, sm_[tid + st], ss_[tid + st]);
            sm_[tid] = m2; ss_[tid] = s2;
        }
        __syncthreads();
    }
    if (tid == 0) { g_M[b] = sm_[0]; g_invS[b] = 1.f / ss_[0]; }
    __threadfence();
    __syncthreads();
    if (tid == 0) atomicExch(&g_row_merge[b], 1);
}

__device__ void role_out(int idx, float* __restrict__ out) {
    int b = idx % BB, seg = idx / BB;
    spin_ge(&g_row_merge[b], 1);
    int tid = threadIdx.x;
    float M = g_M[b], inv = g_invS[b];
    const __half* sg = g_scoreh + (size_t)b * VVP;
    float* orow = out + (size_t)b * VO;
#pragma unroll
    for (int l = 0; l < 4; l++) {
        int c0 = seg * 4096 + l * 1024 + tid * 4;
        if (c0 + 3 < VV) {
            __half2 q0 = *(const __half2*)(sg + c0);
            __half2 q1 = *(const __half2*)(sg + c0 + 2);
            orow[c0 + 0] = __expf(__half2float(__low2half(q0))  - M) * inv;
            orow[c0 + 1] = __expf(__half2float(__high2half(q0)) - M) * inv;
            orow[c0 + 2] = __expf(__half2float(__low2half(q1))  - M) * inv;
            orow[c0 + 3] = __expf(__half2float(__high2half(q1)) - M) * inv;
        } else {
            for (int cc = c0; cc < VV && cc < c0 + 4; cc++)
                orow[cc] = __expf(__half2float(sg[cc]) - M) * inv;
        }
    }
    mark_done(&g_row_out[b]);
}

__device__ void role_tail(int b, const int* __restrict__ idxs,
                          const int* __restrict__ dec,
                          const float* __restrict__ EO,
                          float* __restrict__ out, float* __restrict__ out_sr) {
    extern __shared__ uint32_t dyn[];
    float* pc = (float*)dyn;
    int*   mt = (int*)(pc + TT);
    int*   cntp = (int*)(mt + TT);
    spin_ge(&g_row_out[b], NSEG);
    int tid = threadIdx.x;
    float M = g_M[b], inv = g_invS[b];
    float* orow = out + (size_t)b * VO;
    if (tid == 0) *cntp = 0;
    for (int t2 = tid; t2 < TT; t2 += 256)
        pc[t2] = __expf(g_scraw[b * TT + t2] - M) * inv;
    if (tid < NOOV) orow[VV + tid] = 1e-4f;
    __syncthreads();
    int d = dec[b];
    for (int t2 = tid; t2 < TT; t2 += 256) {
        atomicAdd(&orow[idxs[b * TT + t2]], pc[t2]);
        if (idxs[b * TT + t2] == d) { int p = atomicAdd(cntp, 1); mt[p] = t2; }
    }
    __syncthreads();
    int n = *cntp;
    float scale = (n > 1) ? 1.f / (float)n : 1.f;
    for (int e = tid; e < 2 * HH; e += 256) {
        float acc = 0.f;
        for (int k = 0; k < n; k++) {
            int t2 = mt[k];
            acc += pc[t2] * scale * EO[((size_t)b * TT + t2) * (2 * HH) + e];
        }
        out_sr[b * 2 * HH + e] = acc;
    }
    // zero this row's enc accumulator for the next graph replay
    for (int t2 = tid; t2 < TT; t2 += 256) g_scenc[b * TT + t2] = 0.f;
    __threadfence();
    __syncthreads();
    if (tid == 0) {
        int v = atomicAdd(&g_c_tail, 1);
        if (v == BB - 1) {
            atomicExch(&g_c_gates, 0); atomicExch(&g_c_gru, 0);
            atomicExch(&g_c_tiles, 0); atomicExch(&g_c_tail, 0);
            for (int i = 0; i < BB; i++) {
                atomicExch(&g_row_merge[i], 0);
                atomicExch(&g_row_out[i], 0);
            }
        }
    }
}

// ---------------- fused kernel -----------------------------------------------
__global__ void __launch_bounds__(256, 3) k_fused(
        const int* __restrict__ dec, const float* __restrict__ sr,
        const float* __restrict__ emb, const float* __restrict__ prev,
        const float* __restrict__ W_ih, const float* __restrict__ b_ih,
        const float* __restrict__ W_hh, const float* __restrict__ b_hh,
        const float* __restrict__ Wg, const float* __restrict__ gbias,
        const float* __restrict__ EO, const float* __restrict__ Wc,
        const float* __restrict__ cbias, const int* __restrict__ idxs,
        float* __restrict__ out, float* __restrict__ out_dh,
        float* __restrict__ out_sr) {
    extern __shared__ uint32_t dyn[];
    int bid = blockIdx.x;
    if (bid >= OFF_GRU && bid < OFF_ENC) { role_gru(bid - OFF_GRU, prev, out_dh); return; }
    if (bid >= OFF_TAIL)  { role_tail(bid - OFF_TAIL, idxs, dec, EO, out, out_sr); return; }
    if (bid >= OFF_OUT)   { role_out(bid - OFF_OUT, out); return; }
    if (bid >= OFF_MERGE) { role_merge(bid - OFF_MERGE, idxs); return; }

    // ======== GEMM roles: gates / enc / gemmg, all 32x32-warp fp16 ==========
    uint32_t sbase = (uint32_t)__cvta_generic_to_shared(dyn);
    int tid = threadIdx.x, wid = tid >> 5, lane = tid & 31;
    int g = lane >> 2, t = lane & 3;
    int lr = lane & 7;
    int rowadj = ((lane >> 3) & 1) * 8 + lr;
    int kadj = (lane >> 4) * 8;
    uint32_t st0 = sbase, st1 = sbase + STGB;

    float c[2][4][4];
#pragma unroll
    for (int i = 0; i < 2; i++)
#pragma unroll
        for (int j = 0; j < 4; j++)
#pragma unroll
            for (int q = 0; q < 4; q++) c[i][j][q] = 0.f;

    if (bid < OFF_GRU) {
        // ---------- gates tile 128x64: bx<12 -> gi (K=640), else gh (K=256) --
        int bx = bid;
        bool isGi = bx < 12;
        int n0 = (isGi ? bx : bx - 12) * 64;
        int K  = isGi ? 640 : HH;
        int NIT = K / 32;
        const float* W = (isGi ? W_ih : W_hh) + (size_t)n0 * K;
        const float* bias = isGi ? b_ih : b_hh;
        float* C = isGi ? g_gi : g_gh;
        int wm = (wid & 3) * 32, wn = (wid >> 2) * 32;
        uint32_t relA[2], relB[2];
#pragma unroll
        for (int i = 0; i < 2; i++)
            relA[i] = (uint32_t)((wm + i * 16 + rowadj) * KS2 + kadj) * 2;
#pragma unroll
        for (int j = 0; j < 2; j++)
            relB[j] = (uint32_t)((128 + wn + j * 16 + rowadj) * KS2 + kadj) * 2;

        auto ldg3 = [&](float4 (&buf)[3], int base, int kc) {
#pragma unroll
            for (int q = 0; q < 3; q++) {
                int idx = tid + (base + q) * 256;
                int row = idx >> 3, kp = (idx & 7) * 4;
                int col = kc + kp;
                if (row < 128) {
                    if (isGi) {
                        if (col < 512) buf[q] = *(const float4*)(sr + (size_t)row * 512 + col);
                        else           buf[q] = *(const float4*)(emb + (size_t)dec[row] * EE + col - 512);
                    } else buf[q] = *(const float4*)(prev + (size_t)row * HH + col);
                } else buf[q] = *(const float4*)(W + (size_t)(row - 128) * K + col);
            }
        };
        float4 buf[3];
        ldg3(buf, 0, 0); sts3(buf, 0, st0, tid);
        ldg3(buf, 3, 0); sts3(buf, 3, st0, tid);
        __syncthreads();
        for (int it = 0; it < NIT; it++) {
            uint32_t scur = (it & 1) ? st1 : st0;
            uint32_t snxt = (it & 1) ? st0 : st1;
            bool more = (it + 1 < NIT);
            if (more) ldg3(buf, 0, (it + 1) * 32);
            compute_k16(scur, relA, relB, 0, c);
            if (more) { sts3(buf, 0, snxt, tid); ldg3(buf, 3, (it + 1) * 32); }
            compute_k16(scur, relA, relB, 1, c);
            if (more) sts3(buf, 3, snxt, tid);
            __syncthreads();
        }
#pragma unroll
        for (int i = 0; i < 2; i++) {
            int r = wm + i * 16 + g;
#pragma unroll
            for (int j = 0; j < 4; j++) {
                int col = n0 + wn + j * 8 + 2 * t;
                float b0 = bias[col], b1 = bias[col + 1];
                C[(size_t)r * G3 + col]           = c[i][j][0] + b0;
                C[(size_t)r * G3 + col + 1]       = c[i][j][1] + b1;
                C[(size_t)(r + 8) * G3 + col]     = c[i][j][2] + b0;
                C[(size_t)(r + 8) * G3 + col + 1] = c[i][j][3] + b1;
            }
        }
        mark_done(&g_c_gates);
    } else if (bid >= OFF_GEMG) {
        // ---------- gemmg tile 128x64, K=256, NIT=8 ---------------------------
        int bx = bid - OFF_GEMG;
        spin_ge(&g_c_gru, BB);
        int wm = (wid & 3) * 32, wn = (wid >> 2) * 32;
        const float* W = Wg + (size_t)bx * 64 * HH;
        int wvalid = VV - bx * 64; if (wvalid > 64) wvalid = 64;
        const int NIT = 8;
        uint32_t relA[2], relB[2];
#pragma unroll
        for (int i = 0; i < 2; i++)
            relA[i] = (uint32_t)((wm + i * 16 + rowadj) * KS2 + kadj) * 2;
#pragma unroll
        for (int j = 0; j < 2; j++)
            relB[j] = (uint32_t)((128 + wn + j * 16 + rowadj) * KS2 + kadj) * 2;

        auto ldg3 = [&](float4 (&buf)[3], int base, int kc) {
#pragma unroll
            for (int q = 0; q < 3; q++) {
                int idx = tid + (base + q) * 256;
                int row = idx >> 3, kp = (idx & 7) * 4;
                if (row < 128) buf[q] = *(const float4*)(g_dh + (size_t)row * HH + kc + kp);
                else {
                    int wr = row - 128;
                    if (wr < wvalid) buf[q] = *(const float4*)(W + (size_t)wr * HH + kc + kp);
                    else             buf[q] = make_float4(0.f, 0.f, 0.f, 0.f);
                }
            }
        };
        float4 buf[3];
        ldg3(buf, 0, 0); sts3(buf, 0, st0, tid);
        ldg3(buf, 3, 0); sts3(buf, 3, st0, tid);
        __syncthreads();
        for (int it = 0; it < NIT; it++) {
            uint32_t scur = (it & 1) ? st1 : st0;
            uint32_t snxt = (it & 1) ? st0 : st1;
            bool more = (it + 1 < NIT);
            if (more) ldg3(buf, 0, (it + 1) * 32);
            compute_k16(scur, relA, relB, 0, c);
            if (more) { sts3(buf, 0, snxt, tid); ldg3(buf, 3, (it + 1) * 32); }
            compute_k16(scur, relA, relB, 1, c);
            if (more) sts3(buf, 3, snxt, tid);
            __syncthreads();
        }
        // epilogue: half store + per-tile (max, sumexp)
        int n0 = bx * 64;
        float lm[2][2], ls[2][2];
#pragma unroll
        for (int i = 0; i < 2; i++)
#pragma unroll
            for (int h = 0; h < 2; h++) { lm[i][h] = -1e30f; ls[i][h] = 0.f; }
#pragma unroll
        for (int i = 0; i < 2; i++) {
            int r = wm + i * 16 + g;
#pragma unroll
            for (int j = 0; j < 4; j++) {
                int col = n0 + wn + j * 8 + 2 * t;
                if (col < VV) {
                    bool p1 = (col + 1 < VV);
                    float b0 = gbias[col];
                    float b1 = p1 ? gbias[col + 1] : 0.f;
                    __half2 h02 = __floats2half2_rn(c[i][j][0] + b0, c[i][j][1] + b1);
                    __half2 h23 = __floats2half2_rn(c[i][j][2] + b0, c[i][j][3] + b1);
                    *(__half2*)(g_scoreh + (size_t)r * VVP + col)       = h02;
                    *(__half2*)(g_scoreh + (size_t)(r + 8) * VVP + col) = h23;
                    float w0 = __half2float(__low2half(h02));
                    float w1 = __half2float(__high2half(h02));
                    float w2 = __half2float(__low2half(h23));
                    float w3 = __half2float(__high2half(h23));
                    lm[i][0] = fmaxf(lm[i][0], w0);
                    lm[i][1] = fmaxf(lm[i][1], w2);
                    if (p1) { lm[i][0] = fmaxf(lm[i][0], w1); lm[i][1] = fmaxf(lm[i][1], w3); }
                }
            }
        }
#pragma unroll
        for (int i = 0; i < 2; i++)
#pragma unroll
            for (int j = 0; j < 4; j++) {
                int col = n0 + wn + j * 8 + 2 * t;
                if (col < VV) {
                    bool p1 = (col + 1 < VV);
                    float b0 = gbias[col];
                    float b1 = p1 ? gbias[col + 1] : 0.f;
                    float w0 = __half2float(__float2half_rn(c[i][j][0] + b0));
                    float w2 = __half2float(__float2half_rn(c[i][j][2] + b0));
                    ls[i][0] += __expf(w0 - lm[i][0]);
                    ls[i][1] += __expf(w2 - lm[i][1]);
                    if (p1) {
                        float w1 = __half2float(__float2half_rn(c[i][j][1] + b1));
                        float w3 = __half2float(__float2half_rn(c[i][j][3] + b1));
                        ls[i][0] += __expf(w1 - lm[i][0]);
                        ls[i][1] += __expf(w3 - lm[i][1]);
                    }
                }
            }
        __syncthreads();
        float* redm = (float*)dyn;
        float* reds = redm + 256;
#pragma unroll
        for (int i = 0; i < 2; i++)
#pragma unroll
            for (int h = 0; h < 2; h++) {
                float m = lm[i][h], s = ls[i][h];
#pragma unroll
                for (int off = 1; off <= 2; off <<= 1) {
                    float om = __shfl_xor_sync(0xffffffffu, m, off);
                    float os = __shfl_xor_sync(0xffffffffu, s, off);
                    osm(m, s, om, os);
                }
                if (t == 0) {
                    int row = wm + i * 16 + h * 8 + g;
                    redm[row * 2 + (wid >> 2)] = m;
                    reds[row * 2 + (wid >> 2)] = s;
                }
            }
        __syncthreads();
        if (tid < 128) {
            float m = redm[tid * 2], s = reds[tid * 2];
            osm(m, s, redm[tid * 2 + 1], reds[tid * 2 + 1]);
            g_pmax[tid * NBG + bx] = m;
            g_psum[tid * NBG + bx] = s;
        }
        mark_done(&g_c_tiles);
    } else {
        // ---------- enc tile 64x128, K=512, NIT=16 ----------------------------
        int bx = bid - OFF_ENC;
        int r0 = (bx >> 1) * 64;
        int n0w = (bx & 1) * 128;
        int wm = (wid & 1) * 32, wn = (wid >> 1) * 32;
        const int NIT = 16;
        uint32_t relA[2], relB[2];
#pragma unroll
        for (int i = 0; i < 2; i++)
            relA[i] = (uint32_t)((wm + i * 16 + rowadj) * KS2 + kadj) * 2;
#pragma unroll
        for (int j = 0; j < 2; j++)
            relB[j] = (uint32_t)((64 + wn + j * 16 + rowadj) * KS2 + kadj) * 2;

        auto ldg3 = [&](float4 (&buf)[3], int base, int kc) {
#pragma unroll
            for (int q = 0; q < 3; q++) {
                int idx = tid + (base + q) * 256;
                int row = idx >> 3, kp = (idx & 7) * 4;
                if (row < 64) buf[q] = *(const float4*)(EO + (size_t)(r0 + row) * 512 + kc + kp);
                else          buf[q] = *(const float4*)(Wc + (size_t)(n0w + row - 64) * 512 + kc + kp);
            }
        };
        float4 buf[3];
        ldg3(buf, 0, 0); sts3(buf, 0, st0, tid);
        ldg3(buf, 3, 0); sts3(buf, 3, st0, tid);
        __syncthreads();
        for (int it = 0; it < NIT; it++) {
            uint32_t scur = (it & 1) ? st1 : st0;
            uint32_t snxt = (it & 1) ? st0 : st1;
            bool more = (it + 1 < NIT);
            if (more) ldg3(buf, 0, (it + 1) * 32);
            compute_k16(scur, relA, relB, 0, c);
            if (more) { sts3(buf, 0, snxt, tid); ldg3(buf, 3, (it + 1) * 32); }
            compute_k16(scur, relA, relB, 1, c);
            if (more) sts3(buf, 3, snxt, tid);
            __syncthreads();
        }
        spin_ge(&g_c_gru, BB);
        float rs[2][2] = {{0.f, 0.f}, {0.f, 0.f}};
#pragma unroll
        for (int i = 0; i < 2; i++) {
            int grow = r0 + wm + i * 16 + g;
            int b0r = grow / TT;
            int b1r = (grow + 8) / TT;
#pragma unroll
            for (int j = 0; j < 4; j++) {
                int col = n0w + wn + j * 8 + 2 * t;
                float bi0 = cbias[col], bi1 = cbias[col + 1];
                rs[i][0] += tanhf(c[i][j][0] + bi0) * g_dh[b0r * HH + col]
                          + tanhf(c[i][j][1] + bi1) * g_dh[b0r * HH + col + 1];
                rs[i][1] += tanhf(c[i][j][2] + bi0) * g_dh[b1r * HH + col]
                          + tanhf(c[i][j][3] + bi1) * g_dh[b1r * HH + col + 1];
            }
        }
        __syncthreads();
        float* red = (float*)dyn;            // [64][4]
#pragma unroll
        for (int i = 0; i < 2; i++)
#pragma unroll
            for (int h = 0; h < 2; h++) {
                float v = rs[i][h];
                v += __shfl_xor_sync(0xffffffffu, v, 1);
                v += __shfl_xor_sync(0xffffffffu, v, 2);
                if (t == 0) red[(wm + i * 16 + h * 8 + g) * 4 + (wid >> 1)] = v;
            }
        __syncthreads();
        if (tid < 64) {
            float tot = red[tid * 4] + red[tid * 4 + 1] + red[tid * 4 + 2] + red[tid * 4 + 3];
            atomicAdd(&g_scenc[r0 + tid], tot);
        }
        mark_done(&g_c_tiles);
    }
}

// ---------------- launch ----------------------------------------------------
extern "C" void kernel_launch(void* const* d_in, const int* in_sizes, int n_in,
                              void* d_out, int out_size) {
    const int*   dec  = (const int*)d_in[0];
    const float* EO   = (const float*)d_in[1];
    const int*   idxs = (const int*)d_in[2];
    const float* prev = (const float*)d_in[3];
    const float* sr   = (const float*)d_in[4];
    int off = (n_in >= 17 && in_sizes[5] == 1) ? 1 : 0;
    const float* emb  = (const float*)d_in[5 + off];
    const float* W_ih = (const float*)d_in[6 + off];
    const float* W_hh = (const float*)d_in[7 + off];
    const float* b_ih = (const float*)d_in[8 + off];
    const float* b_hh = (const float*)d_in[9 + off];
    const float* Wg_w = (const float*)d_in[12 + off];
    const float* Wg_b = (const float*)d_in[13 + off];
    const float* Wc_w = (const float*)d_in[14 + off];
    const float* Wc_b = (const float*)d_in[15 + off];

    float* out    = (float*)d_out;
    float* out_dh = out + (size_t)BB * VO;
    float* out_sr = out_dh + (size_t)BB * HH;

    cudaFuncSetAttribute(k_fused, cudaFuncAttributeMaxDynamicSharedMemorySize, DYN_FUSED);

    k_fused<<<NBLK, 256, DYN_FUSED>>>(dec, sr, emb, prev, W_ih, b_ih, W_hh, b_hh,
                                      Wg_w, Wg_b, EO, Wc_w, Wc_b, idxs,
                                      out, out_dh, out_sr);
}